// round 9
// baseline (speedup 1.0000x reference)
#include <cuda_runtime.h>
#include <cuda_bf16.h>
#include <math.h>
#include <stdint.h>

#define Bb 4
#define Mm 4096
#define Dd 768
#define Ee 1536
#define Nn 16
#define KK 3
#define BMr (Bb*Mm)   // 16384 rows

// ---------------- scratch (static device globals; allocation-free) ----------------
__device__ float g_xn   [BMr*Dd];
__device__ float g_xproj[BMr*Ee];   // later reused as gated y
__device__ float g_zs   [BMr*Ee];   // silu(z)
__device__ float g_xpf  [BMr*Ee];
__device__ float g_xpb  [BMr*Ee];
__device__ float g_df   [BMr*Ee];
__device__ float g_dbk  [BMr*Ee];
__device__ float g_yf   [BMr*Ee];
__device__ float g_yb   [BMr*Ee];
__device__ float g_Bpf  [BMr*Nn];
__device__ float g_Cpf  [BMr*Nn];
__device__ float g_Bpb  [BMr*Nn];
__device__ float g_Cpb  [BMr*Nn];
__device__ float g_wcf  [KK*Ee*Ee]; // conv weights repacked [k][o][i]
__device__ float g_wcb  [KK*Ee*Ee];

// ---------------- helpers ----------------
__device__ __forceinline__ float silu_f(float x)     { return x / (1.f + expf(-x)); }
__device__ __forceinline__ float softplus_f(float x) { return (x > 20.f) ? x : log1pf(expf(x)); }

__device__ __forceinline__ uint32_t packbf(float a, float b) {
    __nv_bfloat162 h = __floats2bfloat162_rn(a, b);   // low = a, high = b
    return *reinterpret_cast<uint32_t*>(&h);
}

__device__ __forceinline__ void mma_bf16(float* c, const uint32_t* a, const uint32_t* b) {
    asm volatile(
        "mma.sync.aligned.m16n8k16.row.col.f32.bf16.bf16.f32 "
        "{%0,%1,%2,%3}, {%4,%5,%6,%7}, {%8,%9}, {%0,%1,%2,%3};\n"
        : "+f"(c[0]), "+f"(c[1]), "+f"(c[2]), "+f"(c[3])
        : "r"(a[0]), "r"(a[1]), "r"(a[2]), "r"(a[3]),
          "r"(b[0]), "r"(b[1]));
}

// ---------------- layernorm: one block per row of 768 ----------------
__global__ void ln_kernel(const float* __restrict__ t, const float* __restrict__ g,
                          const float* __restrict__ b, float* __restrict__ xn)
{
    int row = blockIdx.x;
    int tid = threadIdx.x;
    const float* x = t + (size_t)row * Dd;
    float v0 = x[tid], v1 = x[tid + 256], v2 = x[tid + 512];
    float s  = v0 + v1 + v2;
    float sq = v0*v0 + v1*v1 + v2*v2;
    #pragma unroll
    for (int off = 16; off > 0; off >>= 1) {
        s  += __shfl_down_sync(0xffffffffu, s,  off);
        sq += __shfl_down_sync(0xffffffffu, sq, off);
    }
    __shared__ float red[16];
    int warp = tid >> 5, lane = tid & 31;
    if (lane == 0) { red[warp] = s; red[8 + warp] = sq; }
    __syncthreads();
    if (tid == 0) {
        float S = 0.f, Q = 0.f;
        #pragma unroll
        for (int w = 0; w < 8; w++) { S += red[w]; Q += red[8 + w]; }
        red[0] = S; red[8] = Q;
    }
    __syncthreads();
    float mu  = red[0] * (1.f / Dd);
    float var = red[8] * (1.f / Dd) - mu * mu;
    float inv = rsqrtf(var + 1e-5f);
    float* o = xn + (size_t)row * Dd;
    o[tid]       = (v0 - mu) * inv * g[tid]       + b[tid];
    o[tid + 256] = (v1 - mu) * inv * g[tid + 256] + b[tid + 256];
    o[tid + 512] = (v2 - mu) * inv * g[tid + 512] + b[tid + 512];
}

// ================= bf16 tensor-core NT GEMM (R3-proven schedule) =================
// C[M,N] = A[M,K] @ W[N,K]^T + bias (+bias2) [ACT] (+resid)
// 128x128x16 tile, 256 threads, warp grid 4(row)x2(col), 32x64 per warp.
// smem: single buffer, 2x[128][12] half2-words (12.3KB); 2 syncs/tile;
// next-tile LDG prefetch issued after 2nd sync (hidden under mma).
template<int ACT>
__global__ void __launch_bounds__(256)
gemm_tc(const float* __restrict__ A, const float* __restrict__ W,
        const float* __restrict__ bias, const float* __restrict__ bias2,
        const float* __restrict__ resid, float* __restrict__ C,
        int Ntot, int Ktot)
{
    __shared__ uint32_t As[128][12];   // [row][k2] k2 = k/2, 8 words used + 4 pad
    __shared__ uint32_t Bs[128][12];
    int tid  = threadIdx.x;
    int brow = blockIdx.y * 128;
    int bcol = blockIdx.x * 128;
    int w  = tid >> 5, l = tid & 31;
    int rb = (w & 3) * 32;         // warp row base
    int cb = (w >> 2) * 64;        // warp col base
    int g  = l >> 2, tg = l & 3;
    int lr = tid >> 2;             // 0..63
    int lc = (tid & 3) * 4;        // float k offset 0,4,8,12
    int lw = (tid & 3) * 2;        // half2-word offset 0,2,4,6

    const float* Ap0 = A + (size_t)(brow + lr)      * Ktot + lc;
    const float* Ap1 = A + (size_t)(brow + lr + 64) * Ktot + lc;
    const float* Wp0 = W + (size_t)(bcol + lr)      * Ktot + lc;
    const float* Wp1 = W + (size_t)(bcol + lr + 64) * Ktot + lc;

    float acc[2][8][4];
    #pragma unroll
    for (int i = 0; i < 2; i++)
        #pragma unroll
        for (int j = 0; j < 8; j++)
            #pragma unroll
            for (int q = 0; q < 4; q++) acc[i][j][q] = 0.f;

    float4 pa0 = *(const float4*)(Ap0);
    float4 pa1 = *(const float4*)(Ap1);
    float4 pw0 = *(const float4*)(Wp0);
    float4 pw1 = *(const float4*)(Wp1);

    int T = Ktot >> 4;
    for (int kt = 0; kt < T; ++kt) {
        __syncthreads();
        As[lr][lw]          = packbf(pa0.x, pa0.y);
        As[lr][lw + 1]      = packbf(pa0.z, pa0.w);
        As[lr + 64][lw]     = packbf(pa1.x, pa1.y);
        As[lr + 64][lw + 1] = packbf(pa1.z, pa1.w);
        Bs[lr][lw]          = packbf(pw0.x, pw0.y);
        Bs[lr][lw + 1]      = packbf(pw0.z, pw0.w);
        Bs[lr + 64][lw]     = packbf(pw1.x, pw1.y);
        Bs[lr + 64][lw + 1] = packbf(pw1.z, pw1.w);
        __syncthreads();
        if (kt + 1 < T) {
            int k0 = (kt + 1) * 16;
            pa0 = *(const float4*)(Ap0 + k0);
            pa1 = *(const float4*)(Ap1 + k0);
            pw0 = *(const float4*)(Wp0 + k0);
            pw1 = *(const float4*)(Wp1 + k0);
        }
        uint32_t af[2][4], bf[8][2];
        #pragma unroll
        for (int mt = 0; mt < 2; mt++) {
            int r = rb + mt * 16 + g;
            af[mt][0] = As[r    ][tg];
            af[mt][1] = As[r + 8][tg];
            af[mt][2] = As[r    ][tg + 4];
            af[mt][3] = As[r + 8][tg + 4];
        }
        #pragma unroll
        for (int nt = 0; nt < 8; nt++) {
            int n = cb + nt * 8 + g;
            bf[nt][0] = Bs[n][tg];
            bf[nt][1] = Bs[n][tg + 4];
        }
        #pragma unroll
        for (int mt = 0; mt < 2; mt++)
            #pragma unroll
            for (int nt = 0; nt < 8; nt++)
                mma_bf16(acc[mt][nt], af[mt], bf[nt]);
    }

    // epilogue
    #pragma unroll
    for (int mt = 0; mt < 2; mt++) {
        int r0 = brow + rb + mt * 16 + g;
        #pragma unroll
        for (int nt = 0; nt < 8; nt++) {
            int col = bcol + cb + nt * 8 + 2 * tg;
            float b0 = bias[col], b1 = bias[col + 1];
            if (bias2) { b0 += bias2[col]; b1 += bias2[col + 1]; }
            float v0 = acc[mt][nt][0] + b0;
            float v1 = acc[mt][nt][1] + b1;
            float v2 = acc[mt][nt][2] + b0;
            float v3 = acc[mt][nt][3] + b1;
            if (ACT == 1) { v0 = silu_f(v0); v1 = silu_f(v1); v2 = silu_f(v2); v3 = silu_f(v3); }
            if (ACT == 2) { v0 = softplus_f(v0); v1 = softplus_f(v1); v2 = softplus_f(v2); v3 = softplus_f(v3); }
            if (resid) {
                v0 += resid[(size_t)r0 * Ntot + col];
                v1 += resid[(size_t)r0 * Ntot + col + 1];
                v2 += resid[(size_t)(r0 + 8) * Ntot + col];
                v3 += resid[(size_t)(r0 + 8) * Ntot + col + 1];
            }
            *(float2*)&C[(size_t)r0 * Ntot + col]       = make_float2(v0, v1);
            *(float2*)&C[(size_t)(r0 + 8) * Ntot + col] = make_float2(v2, v3);
        }
    }
}

// ---------------- conv weight repack: w[o][i][k] -> out[k][o][i] ----------------
__global__ void repack_conv(const float* __restrict__ w, float* __restrict__ out)
{
    int idx = blockIdx.x * blockDim.x + threadIdx.x;
    if (idx >= Ee*Ee) return;
    int o = idx / Ee, i = idx % Ee;
    #pragma unroll
    for (int k = 0; k < KK; k++)
        out[(size_t)k*Ee*Ee + (size_t)o*Ee + i] = w[((size_t)o*Ee + i)*KK + k];
}

// ---------------- conv-as-GEMM (shifted A gather), bf16, R3 schedule ------------
__global__ void __launch_bounds__(256)
conv_tc(const float* __restrict__ X, const float* __restrict__ Wp,
        const float* __restrict__ bias, float* __restrict__ C)
{
    __shared__ uint32_t As[128][12];
    __shared__ uint32_t Bs[128][12];
    int tid  = threadIdx.x;
    int brow = blockIdx.y * 128;
    int bcol = blockIdx.x * 128;
    int b_ = brow / Mm;
    int m0 = brow % Mm;
    int w  = tid >> 5, l = tid & 31;
    int rb = (w & 3) * 32;
    int cb = (w >> 2) * 64;
    int g  = l >> 2, tg = l & 3;
    int lr = tid >> 2;
    int lc = (tid & 3) * 4;
    int lw = (tid & 3) * 2;

    float acc[2][8][4];
    #pragma unroll
    for (int i = 0; i < 2; i++)
        #pragma unroll
        for (int j = 0; j < 8; j++)
            #pragma unroll
            for (int q = 0; q < 4; q++) acc[i][j][q] = 0.f;

    const int T = (KK * Ee) >> 4; // 288 ktiles
    float4 pa0, pa1, pw0, pw1;

    auto fetch = [&](int kt) {
        int k0  = kt * 16;
        int seg = k0 / Ee;
        int e0  = k0 % Ee;
        int sh  = seg - 1;
        int mA = m0 + lr + sh;
        int mB = m0 + lr + 64 + sh;
        pa0 = (mA >= 0 && mA < Mm)
            ? *(const float4*)(X + (size_t)(b_*Mm + mA)*Ee + e0 + lc)
            : make_float4(0.f,0.f,0.f,0.f);
        pa1 = (mB >= 0 && mB < Mm)
            ? *(const float4*)(X + (size_t)(b_*Mm + mB)*Ee + e0 + lc)
            : make_float4(0.f,0.f,0.f,0.f);
        const float* wseg = Wp + (size_t)seg*Ee*Ee + e0 + lc;
        pw0 = *(const float4*)(wseg + (size_t)(bcol + lr)      * Ee);
        pw1 = *(const float4*)(wseg + (size_t)(bcol + lr + 64) * Ee);
    };

    fetch(0);

    for (int kt = 0; kt < T; ++kt) {
        __syncthreads();
        As[lr][lw]          = packbf(pa0.x, pa0.y);
        As[lr][lw + 1]      = packbf(pa0.z, pa0.w);
        As[lr + 64][lw]     = packbf(pa1.x, pa1.y);
        As[lr + 64][lw + 1] = packbf(pa1.z, pa1.w);
        Bs[lr][lw]          = packbf(pw0.x, pw0.y);
        Bs[lr][lw + 1]      = packbf(pw0.z, pw0.w);
        Bs[lr + 64][lw]     = packbf(pw1.x, pw1.y);
        Bs[lr + 64][lw + 1] = packbf(pw1.z, pw1.w);
        __syncthreads();
        if (kt + 1 < T) fetch(kt + 1);
        uint32_t af[2][4], bf[8][2];
        #pragma unroll
        for (int mt = 0; mt < 2; mt++) {
            int r = rb + mt * 16 + g;
            af[mt][0] = As[r    ][tg];
            af[mt][1] = As[r + 8][tg];
            af[mt][2] = As[r    ][tg + 4];
            af[mt][3] = As[r + 8][tg + 4];
        }
        #pragma unroll
        for (int nt = 0; nt < 8; nt++) {
            int n = cb + nt * 8 + g;
            bf[nt][0] = Bs[n][tg];
            bf[nt][1] = Bs[n][tg + 4];
        }
        #pragma unroll
        for (int mt = 0; mt < 2; mt++)
            #pragma unroll
            for (int nt = 0; nt < 8; nt++)
                mma_bf16(acc[mt][nt], af[mt], bf[nt]);
    }

    #pragma unroll
    for (int mt = 0; mt < 2; mt++) {
        int r0 = brow + rb + mt * 16 + g;
        #pragma unroll
        for (int nt = 0; nt < 8; nt++) {
            int col = bcol + cb + nt * 8 + 2 * tg;
            float b0 = bias[col], b1 = bias[col + 1];
            float v0 = silu_f(acc[mt][nt][0] + b0);
            float v1 = silu_f(acc[mt][nt][1] + b1);
            float v2 = silu_f(acc[mt][nt][2] + b0);
            float v3 = silu_f(acc[mt][nt][3] + b1);
            *(float2*)&C[(size_t)r0 * Ee + col]       = make_float2(v0, v1);
            *(float2*)&C[(size_t)(r0 + 8) * Ee + col] = make_float2(v2, v3);
        }
    }
}

// ---------------- B/C projections: per-row 16+16 outputs ----------------
__global__ void __launch_bounds__(256)
bc_kernel(const float* __restrict__ X,
          const float* __restrict__ WB, const float* __restrict__ bB,
          const float* __restrict__ WC, const float* __restrict__ bC,
          float* __restrict__ Bp, float* __restrict__ Cp)
{
    __shared__ float sWB[Nn][256];
    __shared__ float sWC[Nn][256];
    int tid = threadIdx.x;
    int row = blockIdx.x * 256 + tid;
    float accB[Nn], accC[Nn];
    #pragma unroll
    for (int n = 0; n < Nn; n++) { accB[n] = 0.f; accC[n] = 0.f; }

    for (int ec = 0; ec < Ee; ec += 256) {
        __syncthreads();
        #pragma unroll
        for (int q = 0; q < 4; q++) {
            int f4 = q * 256 + tid;
            int n  = f4 >> 6;
            int e4 = (f4 & 63) * 4;
            *(float4*)&sWB[n][e4] = *(const float4*)(WB + (size_t)n*Ee + ec + e4);
            *(float4*)&sWC[n][e4] = *(const float4*)(WC + (size_t)n*Ee + ec + e4);
        }
        __syncthreads();
        for (int e = 0; e < 256; e += 4) {
            float4 xv = *(const float4*)(X + (size_t)row*Ee + ec + e);
            #pragma unroll
            for (int n = 0; n < Nn; n++) {
                float4 wb = *(const float4*)&sWB[n][e];
                float4 wc = *(const float4*)&sWC[n][e];
                accB[n] = fmaf(xv.x, wb.x, accB[n]);
                accB[n] = fmaf(xv.y, wb.y, accB[n]);
                accB[n] = fmaf(xv.z, wb.z, accB[n]);
                accB[n] = fmaf(xv.w, wb.w, accB[n]);
                accC[n] = fmaf(xv.x, wc.x, accC[n]);
                accC[n] = fmaf(xv.y, wc.y, accC[n]);
                accC[n] = fmaf(xv.z, wc.z, accC[n]);
                accC[n] = fmaf(xv.w, wc.w, accC[n]);
            }
        }
    }
    #pragma unroll
    for (int n = 0; n < Nn; n++) {
        Bp[(size_t)row*Nn + n] = accB[n] + bB[n];
        Cp[(size_t)row*Nn + n] = accC[n] + bC[n];
    }
}

// ---------------- scan: both directions in one launch; thread = one e ----------------
__global__ void __launch_bounds__(256)
scan_kernel(const float* __restrict__ Xf, const float* __restrict__ Df,
            const float* __restrict__ Bpf, const float* __restrict__ Cpf,
            const float* __restrict__ Af,  float* __restrict__ Yf,
            const float* __restrict__ Xb, const float* __restrict__ Db,
            const float* __restrict__ Bpb, const float* __restrict__ Cpb,
            const float* __restrict__ Ab,  float* __restrict__ Yb)
{
    int dir = blockIdx.z;
    const float *X, *Dl, *Bp, *Cp, *A;
    float* Y;
    if (dir == 0) { X = Xf; Dl = Df; Bp = Bpf; Cp = Cpf; A = Af; Y = Yf; }
    else          { X = Xb; Dl = Db; Bp = Bpb; Cp = Cpb; A = Ab; Y = Yb; }
    bool rev = (dir == 1);

    int b_  = blockIdx.y;
    int tid = threadIdx.x;
    int e   = blockIdx.x * 256 + tid;
    size_t baseRow = (size_t)b_ * Mm;

    float a[Nn];
    #pragma unroll
    for (int q = 0; q < 4; q++) {
        float4 av = *(const float4*)(A + (size_t)e*Nn + q*4);
        a[q*4+0] = av.x; a[q*4+1] = av.y; a[q*4+2] = av.z; a[q*4+3] = av.w;
    }
    float h[Nn];
    #pragma unroll
    for (int n = 0; n < Nn; n++) h[n] = 0.f;

    __shared__ float sBC[2][8][32];
    int ls = tid >> 5;
    int ln = tid & 31;

    float xb[8], db[8];
    #pragma unroll
    for (int s = 0; s < 8; s++) {
        int m = rev ? (Mm - 1 - s) : s;
        size_t idx = (baseRow + m) * Ee + e;
        xb[s] = X[idx]; db[s] = Dl[idx];
    }
    {
        int m = rev ? (Mm - 1 - ls) : ls;
        sBC[0][ls][ln] = (ln < Nn) ? Bp[(baseRow + m)*Nn + ln]
                                   : Cp[(baseRow + m)*Nn + (ln - Nn)];
    }
    __syncthreads();

    const int NCH = Mm / 8;
    for (int c = 0; c < NCH; ++c) {
        int buf = c & 1;
        float nx[8], nd[8], nbc = 0.f;
        bool more = (c + 1 < NCH);
        if (more) {
            #pragma unroll
            for (int s = 0; s < 8; s++) {
                int t = (c + 1) * 8 + s;
                int m = rev ? (Mm - 1 - t) : t;
                size_t idx = (baseRow + m) * Ee + e;
                nx[s] = X[idx]; nd[s] = Dl[idx];
            }
            int t = (c + 1) * 8 + ls;
            int m = rev ? (Mm - 1 - t) : t;
            nbc = (ln < Nn) ? Bp[(baseRow + m)*Nn + ln]
                            : Cp[(baseRow + m)*Nn + (ln - Nn)];
        }
        #pragma unroll
        for (int s = 0; s < 8; s++) {
            float dv = db[s], xv = xb[s];
            float dx = dv * xv;
            float yv0 = 0.f, yv1 = 0.f;
            #pragma unroll
            for (int n = 0; n < Nn; n += 2) {
                float Bn0 = sBC[buf][s][n];
                float Cn0 = sBC[buf][s][Nn + n];
                float Bn1 = sBC[buf][s][n + 1];
                float Cn1 = sBC[buf][s][Nn + n + 1];
                h[n]     = fmaf(dv * a[n],     h[n],     dx * Bn0);
                h[n + 1] = fmaf(dv * a[n + 1], h[n + 1], dx * Bn1);
                yv0 = fmaf(h[n],     Cn0, yv0);
                yv1 = fmaf(h[n + 1], Cn1, yv1);
            }
            int t = c * 8 + s;
            int m = rev ? (Mm - 1 - t) : t;
            Y[(baseRow + m) * Ee + e] = yv0 + yv1;
        }
        if (more) {
            #pragma unroll
            for (int s = 0; s < 8; s++) { xb[s] = nx[s]; db[s] = nd[s]; }
            sBC[buf ^ 1][ls][ln] = nbc;
        }
        __syncthreads();
    }
}

// ---------------- gate multiply ----------------
__global__ void mul_kernel(const float4* __restrict__ a, const float4* __restrict__ b,
                           const float4* __restrict__ z, float4* __restrict__ o, int n4)
{
    for (int i = blockIdx.x * blockDim.x + threadIdx.x; i < n4; i += gridDim.x * blockDim.x) {
        float4 A = a[i], Bv = b[i], Z = z[i], O;
        O.x = (A.x + Bv.x) * Z.x;
        O.y = (A.y + Bv.y) * Z.y;
        O.z = (A.z + Bv.z) * Z.z;
        O.w = (A.w + Bv.w) * Z.w;
        o[i] = O;
    }
}

// ---------------- launch ----------------
extern "C" void kernel_launch(void* const* d_in, const int* in_sizes, int n_in,
                              void* d_out, int out_size)
{
    const float* t    = (const float*)d_in[0];
    const float* ln_g = (const float*)d_in[1];
    const float* ln_b = (const float*)d_in[2];
    const float* Wx   = (const float*)d_in[3];
    const float* bx   = (const float*)d_in[4];
    const float* Wz   = (const float*)d_in[5];
    const float* bz   = (const float*)d_in[6];
    const float* Wcf  = (const float*)d_in[7];
    const float* bcf  = (const float*)d_in[8];
    const float* Wcb  = (const float*)d_in[9];
    const float* bcb  = (const float*)d_in[10];
    const float* WBf  = (const float*)d_in[11];
    const float* bBf  = (const float*)d_in[12];
    const float* WCf  = (const float*)d_in[13];
    const float* bCf  = (const float*)d_in[14];
    const float* WDf  = (const float*)d_in[15];
    const float* bDf  = (const float*)d_in[16];
    const float* WBb  = (const float*)d_in[17];
    const float* bBb  = (const float*)d_in[18];
    const float* WCb  = (const float*)d_in[19];
    const float* bCb  = (const float*)d_in[20];
    const float* WDb  = (const float*)d_in[21];
    const float* bDb  = (const float*)d_in[22];
    const float* Abf  = (const float*)d_in[23];
    const float* Abb  = (const float*)d_in[24];
    const float* dbf  = (const float*)d_in[25];
    const float* dbb  = (const float*)d_in[26];
    const float* WT   = (const float*)d_in[27];
    const float* bT   = (const float*)d_in[28];
    float* out = (float*)d_out;

    void *p_xn, *p_xproj, *p_zs, *p_xpf, *p_xpb, *p_df, *p_dbk, *p_yf, *p_yb;
    void *p_Bpf, *p_Cpf, *p_Bpb, *p_Cpb, *p_wcf, *p_wcb;
    cudaGetSymbolAddress(&p_xn, g_xn);
    cudaGetSymbolAddress(&p_xproj, g_xproj);
    cudaGetSymbolAddress(&p_zs, g_zs);
    cudaGetSymbolAddress(&p_xpf, g_xpf);
    cudaGetSymbolAddress(&p_xpb, g_xpb);
    cudaGetSymbolAddress(&p_df, g_df);
    cudaGetSymbolAddress(&p_dbk, g_dbk);
    cudaGetSymbolAddress(&p_yf, g_yf);
    cudaGetSymbolAddress(&p_yb, g_yb);
    cudaGetSymbolAddress(&p_Bpf, g_Bpf);
    cudaGetSymbolAddress(&p_Cpf, g_Cpf);
    cudaGetSymbolAddress(&p_Bpb, g_Bpb);
    cudaGetSymbolAddress(&p_Cpb, g_Cpb);
    cudaGetSymbolAddress(&p_wcf, g_wcf);
    cudaGetSymbolAddress(&p_wcb, g_wcb);

    float* xn    = (float*)p_xn;
    float* xproj = (float*)p_xproj;
    float* zs    = (float*)p_zs;
    float* xpf   = (float*)p_xpf;
    float* xpb   = (float*)p_xpb;
    float* df    = (float*)p_df;
    float* dbk   = (float*)p_dbk;
    float* yf    = (float*)p_yf;
    float* yb    = (float*)p_yb;
    float* Bpf   = (float*)p_Bpf;
    float* Cpf   = (float*)p_Cpf;
    float* Bpb   = (float*)p_Bpb;
    float* Cpb   = (float*)p_Cpb;
    float* wcf   = (float*)p_wcf;
    float* wcb   = (float*)p_wcb;

    // 1. layernorm
    ln_kernel<<<BMr, 256>>>(t, ln_g, ln_b, xn);

    // 2. x_proj and silu(z)
    dim3 gEB(Ee/128, BMr/128);
    gemm_tc<0><<<gEB, 256>>>(xn, Wx, bx, nullptr, nullptr, xproj, Ee, Dd);
    gemm_tc<1><<<gEB, 256>>>(xn, Wz, bz, nullptr, nullptr, zs,    Ee, Dd);

    // 3. conv weight repack + convs (fused bias + silu)
    repack_conv<<<(Ee*Ee + 255)/256, 256>>>(Wcf, wcf);
    repack_conv<<<(Ee*Ee + 255)/256, 256>>>(Wcb, wcb);
    conv_tc<<<gEB, 256>>>(xproj, wcf, bcf, xpf);
    conv_tc<<<gEB, 256>>>(xproj, wcb, bcb, xpb);

    // 4. B/C projections
    bc_kernel<<<BMr/256, 256>>>(xpf, WBf, bBf, WCf, bCf, Bpf, Cpf);
    bc_kernel<<<BMr/256, 256>>>(xpb, WBb, bBb, WCb, bCb, Bpb, Cpb);

    // 5. Delta (softplus)
    gemm_tc<2><<<gEB, 256>>>(xpf, WDf, bDf, dbf, nullptr, df,  Ee, Ee);
    gemm_tc<2><<<gEB, 256>>>(xpb, WDb, bDb, dbb, nullptr, dbk, Ee, Ee);

    // 6. scans
    scan_kernel<<<dim3(Ee/256, Bb, 2), 256>>>(xpf, df, Bpf, Cpf, Abf, yf,
                                              xpb, dbk, Bpb, Cpb, Abb, yb);

    // 7. gate multiply
    mul_kernel<<<2048, 256>>>((const float4*)yf, (const float4*)yb,
                              (const float4*)zs, (float4*)xproj,
                              (BMr * Ee) / 4);

    // 8. final projection + residual
    gemm_tc<0><<<dim3(Dd/128, BMr/128), 256>>>(xproj, WT, bT, nullptr, t, out, Dd, Ee);
}

// round 11
// speedup vs baseline: 1.2912x; 1.2912x over previous
#include <cuda_runtime.h>
#include <cuda_bf16.h>
#include <math.h>
#include <stdint.h>

#define Bb 4
#define Mm 4096
#define Dd 768
#define Ee 1536
#define Nn 16
#define KK 3
#define BMr (Bb*Mm)   // 16384 rows

// ---------------- scratch (static device globals; allocation-free) ----------------
__device__ __nv_bfloat16 g_xn_h [BMr*Dd];     // LN output (GEMM A operand)
__device__ __nv_bfloat16 g_xpj_h[BMr*Ee];     // x_proj (conv A operand)
__device__ float         g_zs   [BMr*Ee];     // silu(z) f32 (gate input)
__device__ float         g_xpf  [BMr*Ee];     // conv outputs f32 (bc + scan)
__device__ float         g_xpb  [BMr*Ee];
__device__ __nv_bfloat16 g_xpf_h[BMr*Ee];     // conv outputs bf16 (delta-GEMM A)
__device__ __nv_bfloat16 g_xpb_h[BMr*Ee];
__device__ float         g_df   [BMr*Ee];
__device__ float         g_dbk  [BMr*Ee];
__device__ float         g_yf   [BMr*Ee];
__device__ float         g_yb   [BMr*Ee];
__device__ __nv_bfloat16 g_gate_h[BMr*Ee];    // (yf+yb)*silu(z) bf16 (final GEMM A)
__device__ float g_Bpf[BMr*Nn], g_Cpf[BMr*Nn], g_Bpb[BMr*Nn], g_Cpb[BMr*Nn];
// bf16 weights
__device__ __nv_bfloat16 g_wcf_h[KK*Ee*Ee];   // conv weights repacked [k][o][i]
__device__ __nv_bfloat16 g_wcb_h[KK*Ee*Ee];
__device__ __nv_bfloat16 g_wx_h [Ee*Dd];
__device__ __nv_bfloat16 g_wz_h [Ee*Dd];
__device__ __nv_bfloat16 g_wdf_h[Ee*Ee];
__device__ __nv_bfloat16 g_wdb_h[Ee*Ee];
__device__ __nv_bfloat16 g_wt_h [Dd*Ee];

// ---------------- helpers ----------------
__device__ __forceinline__ float silu_f(float x)     { return x / (1.f + expf(-x)); }
__device__ __forceinline__ float softplus_f(float x) { return (x > 20.f) ? x : log1pf(expf(x)); }

__device__ __forceinline__ uint32_t packbf(float a, float b) {
    __nv_bfloat162 h = __floats2bfloat162_rn(a, b);   // low = a, high = b
    return *reinterpret_cast<uint32_t*>(&h);
}

__device__ __forceinline__ void mma_bf16(float* c, const uint32_t* a, const uint32_t* b) {
    asm volatile(
        "mma.sync.aligned.m16n8k16.row.col.f32.bf16.bf16.f32 "
        "{%0,%1,%2,%3}, {%4,%5,%6,%7}, {%8,%9}, {%0,%1,%2,%3};\n"
        : "+f"(c[0]), "+f"(c[1]), "+f"(c[2]), "+f"(c[3])
        : "r"(a[0]), "r"(a[1]), "r"(a[2]), "r"(a[3]),
          "r"(b[0]), "r"(b[1]));
}

// ---------------- f32 -> bf16 bulk convert (weights) ----------------
__global__ void cvt_kernel(const float4* __restrict__ in, uint2* __restrict__ out, int n4)
{
    int i = blockIdx.x * blockDim.x + threadIdx.x;
    if (i < n4) {
        float4 v = in[i];
        out[i] = make_uint2(packbf(v.x, v.y), packbf(v.z, v.w));
    }
}

// ---------------- conv weight repack + convert: w[o][i][k] -> out_bf16[k][o][i] ----
__global__ void repack_conv(const float* __restrict__ w, __nv_bfloat16* __restrict__ out)
{
    int idx = blockIdx.x * blockDim.x + threadIdx.x;
    if (idx >= Ee*Ee) return;
    int o = idx / Ee, i = idx % Ee;
    #pragma unroll
    for (int k = 0; k < KK; k++)
        out[(size_t)k*Ee*Ee + (size_t)o*Ee + i] = __float2bfloat16(w[((size_t)o*Ee + i)*KK + k]);
}

// ---------------- layernorm: one block per row of 768; bf16 output ----------------
__global__ void ln_kernel(const float* __restrict__ t, const float* __restrict__ g,
                          const float* __restrict__ b, __nv_bfloat16* __restrict__ xn)
{
    int row = blockIdx.x;
    int tid = threadIdx.x;
    const float* x = t + (size_t)row * Dd;
    float v0 = x[tid], v1 = x[tid + 256], v2 = x[tid + 512];
    float s  = v0 + v1 + v2;
    float sq = v0*v0 + v1*v1 + v2*v2;
    #pragma unroll
    for (int off = 16; off > 0; off >>= 1) {
        s  += __shfl_down_sync(0xffffffffu, s,  off);
        sq += __shfl_down_sync(0xffffffffu, sq, off);
    }
    __shared__ float red[16];
    int warp = tid >> 5, lane = tid & 31;
    if (lane == 0) { red[warp] = s; red[8 + warp] = sq; }
    __syncthreads();
    if (tid == 0) {
        float S = 0.f, Q = 0.f;
        #pragma unroll
        for (int w = 0; w < 8; w++) { S += red[w]; Q += red[8 + w]; }
        red[0] = S; red[8] = Q;
    }
    __syncthreads();
    float mu  = red[0] * (1.f / Dd);
    float var = red[8] * (1.f / Dd) - mu * mu;
    float inv = rsqrtf(var + 1e-5f);
    __nv_bfloat16* o = xn + (size_t)row * Dd;
    o[tid]       = __float2bfloat16((v0 - mu) * inv * g[tid]       + b[tid]);
    o[tid + 256] = __float2bfloat16((v1 - mu) * inv * g[tid + 256] + b[tid + 256]);
    o[tid + 512] = __float2bfloat16((v2 - mu) * inv * g[tid + 512] + b[tid + 512]);
}

// ================= bf16-everywhere tensor-core NT GEMM (R3 schedule) =============
// C[M,N] = A[M,K] @ W[N,K]^T + bias (+bias2) [ACT] (+resid)
// A, W bf16 in gmem. 128x128x16 tile, 256 threads, warp grid 4x2, 32x64/warp.
// Loader: lr=tid&127 row, lhf=tid>>7 k-half; 1 LDG.128 + 1 STS.128 per operand.
// smem [128][12] words (8 used + 4 pad): STS and fragment LDS conflict-free.
// OUT: 0 = f32 only, 1 = bf16 only, 2 = both.
template<int ACT, int OUT>
__global__ void __launch_bounds__(256)
gemm_bf(const __nv_bfloat16* __restrict__ A, const __nv_bfloat16* __restrict__ W,
        const float* __restrict__ bias, const float* __restrict__ bias2,
        const float* __restrict__ resid, float* __restrict__ C,
        __nv_bfloat16* __restrict__ Ch, int Ntot, int Ktot)
{
    __shared__ uint32_t As[128][12];
    __shared__ uint32_t Bs[128][12];
    int tid  = threadIdx.x;
    int brow = blockIdx.y * 128;
    int bcol = blockIdx.x * 128;
    int w  = tid >> 5, l = tid & 31;
    int rb = (w & 3) * 32;
    int cb = (w >> 2) * 64;
    int g  = l >> 2, tg = l & 3;
    int lr  = tid & 127;        // row 0..127
    int lhf = tid >> 7;         // k-half: 0 -> halves 0..7, 1 -> halves 8..15

    const __nv_bfloat16* Ap = A + (size_t)(brow + lr) * Ktot + lhf * 8;
    const __nv_bfloat16* Wp = W + (size_t)(bcol + lr) * Ktot + lhf * 8;

    float acc[2][8][4];
    #pragma unroll
    for (int i = 0; i < 2; i++)
        #pragma unroll
        for (int j = 0; j < 8; j++)
            #pragma unroll
            for (int q = 0; q < 4; q++) acc[i][j][q] = 0.f;

    uint4 pa = *(const uint4*)Ap;
    uint4 pw = *(const uint4*)Wp;

    int T = Ktot >> 4;
    for (int kt = 0; kt < T; ++kt) {
        __syncthreads();
        *(uint4*)&As[lr][lhf * 4] = pa;
        *(uint4*)&Bs[lr][lhf * 4] = pw;
        __syncthreads();
        if (kt + 1 < T) {
            pa = *(const uint4*)(Ap + (kt + 1) * 16);
            pw = *(const uint4*)(Wp + (kt + 1) * 16);
        }
        uint32_t af[2][4], bf[8][2];
        #pragma unroll
        for (int mt = 0; mt < 2; mt++) {
            int r = rb + mt * 16 + g;
            af[mt][0] = As[r    ][tg];
            af[mt][1] = As[r + 8][tg];
            af[mt][2] = As[r    ][tg + 4];
            af[mt][3] = As[r + 8][tg + 4];
        }
        #pragma unroll
        for (int nt = 0; nt < 8; nt++) {
            int n = cb + nt * 8 + g;
            bf[nt][0] = Bs[n][tg];
            bf[nt][1] = Bs[n][tg + 4];
        }
        #pragma unroll
        for (int mt = 0; mt < 2; mt++)
            #pragma unroll
            for (int nt = 0; nt < 8; nt++)
                mma_bf16(acc[mt][nt], af[mt], bf[nt]);
    }

    // epilogue
    #pragma unroll
    for (int mt = 0; mt < 2; mt++) {
        int r0 = brow + rb + mt * 16 + g;
        #pragma unroll
        for (int nt = 0; nt < 8; nt++) {
            int col = bcol + cb + nt * 8 + 2 * tg;
            float b0 = bias[col], b1 = bias[col + 1];
            if (bias2) { b0 += bias2[col]; b1 += bias2[col + 1]; }
            float v0 = acc[mt][nt][0] + b0;
            float v1 = acc[mt][nt][1] + b1;
            float v2 = acc[mt][nt][2] + b0;
            float v3 = acc[mt][nt][3] + b1;
            if (ACT == 1) { v0 = silu_f(v0); v1 = silu_f(v1); v2 = silu_f(v2); v3 = silu_f(v3); }
            if (ACT == 2) { v0 = softplus_f(v0); v1 = softplus_f(v1); v2 = softplus_f(v2); v3 = softplus_f(v3); }
            if (resid) {
                v0 += resid[(size_t)r0 * Ntot + col];
                v1 += resid[(size_t)r0 * Ntot + col + 1];
                v2 += resid[(size_t)(r0 + 8) * Ntot + col];
                v3 += resid[(size_t)(r0 + 8) * Ntot + col + 1];
            }
            if (OUT != 1) {
                *(float2*)&C[(size_t)r0 * Ntot + col]       = make_float2(v0, v1);
                *(float2*)&C[(size_t)(r0 + 8) * Ntot + col] = make_float2(v2, v3);
            }
            if (OUT != 0) {
                *(uint32_t*)&Ch[(size_t)r0 * Ntot + col]       = packbf(v0, v1);
                *(uint32_t*)&Ch[(size_t)(r0 + 8) * Ntot + col] = packbf(v2, v3);
            }
        }
    }
}

// ---------------- conv-as-GEMM (shifted A gather), bf16 operands ----------------
// Dual output: f32 (bc + scan) and bf16 (delta-GEMM A operand). Fused bias+silu.
__global__ void __launch_bounds__(256)
conv_bf(const __nv_bfloat16* __restrict__ X, const __nv_bfloat16* __restrict__ Wp,
        const float* __restrict__ bias, float* __restrict__ C,
        __nv_bfloat16* __restrict__ Ch)
{
    __shared__ uint32_t As[128][12];
    __shared__ uint32_t Bs[128][12];
    int tid  = threadIdx.x;
    int brow = blockIdx.y * 128;
    int bcol = blockIdx.x * 128;
    int b_ = brow / Mm;
    int m0 = brow % Mm;
    int w  = tid >> 5, l = tid & 31;
    int rb = (w & 3) * 32;
    int cb = (w >> 2) * 64;
    int g  = l >> 2, tg = l & 3;
    int lr  = tid & 127;
    int lhf = tid >> 7;

    float acc[2][8][4];
    #pragma unroll
    for (int i = 0; i < 2; i++)
        #pragma unroll
        for (int j = 0; j < 8; j++)
            #pragma unroll
            for (int q = 0; q < 4; q++) acc[i][j][q] = 0.f;

    const int T = (KK * Ee) >> 4; // 288 ktiles
    uint4 pa, pw;

    auto fetch = [&](int kt) {
        int k0  = kt * 16;
        int seg = k0 / Ee;
        int e0  = k0 % Ee;
        int sh  = seg - 1;
        int mA = m0 + lr + sh;
        pa = (mA >= 0 && mA < Mm)
           ? *(const uint4*)(X + (size_t)(b_*Mm + mA)*Ee + e0 + lhf*8)
           : make_uint4(0u,0u,0u,0u);
        pw = *(const uint4*)(Wp + ((size_t)seg*Ee + bcol + lr)*Ee + e0 + lhf*8);
    };

    fetch(0);

    for (int kt = 0; kt < T; ++kt) {
        __syncthreads();
        *(uint4*)&As[lr][lhf * 4] = pa;
        *(uint4*)&Bs[lr][lhf * 4] = pw;
        __syncthreads();
        if (kt + 1 < T) fetch(kt + 1);
        uint32_t af[2][4], bf[8][2];
        #pragma unroll
        for (int mt = 0; mt < 2; mt++) {
            int r = rb + mt * 16 + g;
            af[mt][0] = As[r    ][tg];
            af[mt][1] = As[r + 8][tg];
            af[mt][2] = As[r    ][tg + 4];
            af[mt][3] = As[r + 8][tg + 4];
        }
        #pragma unroll
        for (int nt = 0; nt < 8; nt++) {
            int n = cb + nt * 8 + g;
            bf[nt][0] = Bs[n][tg];
            bf[nt][1] = Bs[n][tg + 4];
        }
        #pragma unroll
        for (int mt = 0; mt < 2; mt++)
            #pragma unroll
            for (int nt = 0; nt < 8; nt++)
                mma_bf16(acc[mt][nt], af[mt], bf[nt]);
    }

    #pragma unroll
    for (int mt = 0; mt < 2; mt++) {
        int r0 = brow + rb + mt * 16 + g;
        #pragma unroll
        for (int nt = 0; nt < 8; nt++) {
            int col = bcol + cb + nt * 8 + 2 * tg;
            float b0 = bias[col], b1 = bias[col + 1];
            float v0 = silu_f(acc[mt][nt][0] + b0);
            float v1 = silu_f(acc[mt][nt][1] + b1);
            float v2 = silu_f(acc[mt][nt][2] + b0);
            float v3 = silu_f(acc[mt][nt][3] + b1);
            *(float2*)&C[(size_t)r0 * Ee + col]       = make_float2(v0, v1);
            *(float2*)&C[(size_t)(r0 + 8) * Ee + col] = make_float2(v2, v3);
            *(uint32_t*)&Ch[(size_t)r0 * Ee + col]       = packbf(v0, v1);
            *(uint32_t*)&Ch[(size_t)(r0 + 8) * Ee + col] = packbf(v2, v3);
        }
    }
}

// ---------------- B/C projections: per-row 16+16 outputs (f32 inputs) ------------
__global__ void __launch_bounds__(256)
bc_kernel(const float* __restrict__ X,
          const float* __restrict__ WB, const float* __restrict__ bB,
          const float* __restrict__ WC, const float* __restrict__ bC,
          float* __restrict__ Bp, float* __restrict__ Cp)
{
    __shared__ float sWB[Nn][256];
    __shared__ float sWC[Nn][256];
    int tid = threadIdx.x;
    int row = blockIdx.x * 256 + tid;
    float accB[Nn], accC[Nn];
    #pragma unroll
    for (int n = 0; n < Nn; n++) { accB[n] = 0.f; accC[n] = 0.f; }

    for (int ec = 0; ec < Ee; ec += 256) {
        __syncthreads();
        #pragma unroll
        for (int q = 0; q < 4; q++) {
            int f4 = q * 256 + tid;
            int n  = f4 >> 6;
            int e4 = (f4 & 63) * 4;
            *(float4*)&sWB[n][e4] = *(const float4*)(WB + (size_t)n*Ee + ec + e4);
            *(float4*)&sWC[n][e4] = *(const float4*)(WC + (size_t)n*Ee + ec + e4);
        }
        __syncthreads();
        for (int e = 0; e < 256; e += 4) {
            float4 xv = *(const float4*)(X + (size_t)row*Ee + ec + e);
            #pragma unroll
            for (int n = 0; n < Nn; n++) {
                float4 wb = *(const float4*)&sWB[n][e];
                float4 wc = *(const float4*)&sWC[n][e];
                accB[n] = fmaf(xv.x, wb.x, accB[n]);
                accB[n] = fmaf(xv.y, wb.y, accB[n]);
                accB[n] = fmaf(xv.z, wb.z, accB[n]);
                accB[n] = fmaf(xv.w, wb.w, accB[n]);
                accC[n] = fmaf(xv.x, wc.x, accC[n]);
                accC[n] = fmaf(xv.y, wc.y, accC[n]);
                accC[n] = fmaf(xv.z, wc.z, accC[n]);
                accC[n] = fmaf(xv.w, wc.w, accC[n]);
            }
        }
    }
    #pragma unroll
    for (int n = 0; n < Nn; n++) {
        Bp[(size_t)row*Nn + n] = accB[n] + bB[n];
        Cp[(size_t)row*Nn + n] = accC[n] + bC[n];
    }
}

// ---------------- scan: both directions in one launch; thread = one e ----------------
__global__ void __launch_bounds__(256)
scan_kernel(const float* __restrict__ Xf, const float* __restrict__ Df,
            const float* __restrict__ Bpf, const float* __restrict__ Cpf,
            const float* __restrict__ Af,  float* __restrict__ Yf,
            const float* __restrict__ Xb, const float* __restrict__ Db,
            const float* __restrict__ Bpb, const float* __restrict__ Cpb,
            const float* __restrict__ Ab,  float* __restrict__ Yb)
{
    int dir = blockIdx.z;
    const float *X, *Dl, *Bp, *Cp, *A;
    float* Y;
    if (dir == 0) { X = Xf; Dl = Df; Bp = Bpf; Cp = Cpf; A = Af; Y = Yf; }
    else          { X = Xb; Dl = Db; Bp = Bpb; Cp = Cpb; A = Ab; Y = Yb; }
    bool rev = (dir == 1);

    int b_  = blockIdx.y;
    int tid = threadIdx.x;
    int e   = blockIdx.x * 256 + tid;
    size_t baseRow = (size_t)b_ * Mm;

    float a[Nn];
    #pragma unroll
    for (int q = 0; q < 4; q++) {
        float4 av = *(const float4*)(A + (size_t)e*Nn + q*4);
        a[q*4+0] = av.x; a[q*4+1] = av.y; a[q*4+2] = av.z; a[q*4+3] = av.w;
    }
    float h[Nn];
    #pragma unroll
    for (int n = 0; n < Nn; n++) h[n] = 0.f;

    __shared__ float sBC[2][8][32];
    int ls = tid >> 5;
    int ln = tid & 31;

    float xb[8], db[8];
    #pragma unroll
    for (int s = 0; s < 8; s++) {
        int m = rev ? (Mm - 1 - s) : s;
        size_t idx = (baseRow + m) * Ee + e;
        xb[s] = X[idx]; db[s] = Dl[idx];
    }
    {
        int m = rev ? (Mm - 1 - ls) : ls;
        sBC[0][ls][ln] = (ln < Nn) ? Bp[(baseRow + m)*Nn + ln]
                                   : Cp[(baseRow + m)*Nn + (ln - Nn)];
    }
    __syncthreads();

    const int NCH = Mm / 8;
    for (int c = 0; c < NCH; ++c) {
        int buf = c & 1;
        float nx[8], nd[8], nbc = 0.f;
        bool more = (c + 1 < NCH);
        if (more) {
            #pragma unroll
            for (int s = 0; s < 8; s++) {
                int t = (c + 1) * 8 + s;
                int m = rev ? (Mm - 1 - t) : t;
                size_t idx = (baseRow + m) * Ee + e;
                nx[s] = X[idx]; nd[s] = Dl[idx];
            }
            int t = (c + 1) * 8 + ls;
            int m = rev ? (Mm - 1 - t) : t;
            nbc = (ln < Nn) ? Bp[(baseRow + m)*Nn + ln]
                            : Cp[(baseRow + m)*Nn + (ln - Nn)];
        }
        #pragma unroll
        for (int s = 0; s < 8; s++) {
            float dv = db[s], xv = xb[s];
            float dx = dv * xv;
            float yv0 = 0.f, yv1 = 0.f;
            #pragma unroll
            for (int n = 0; n < Nn; n += 2) {
                float Bn0 = sBC[buf][s][n];
                float Cn0 = sBC[buf][s][Nn + n];
                float Bn1 = sBC[buf][s][n + 1];
                float Cn1 = sBC[buf][s][Nn + n + 1];
                h[n]     = fmaf(dv * a[n],     h[n],     dx * Bn0);
                h[n + 1] = fmaf(dv * a[n + 1], h[n + 1], dx * Bn1);
                yv0 = fmaf(h[n],     Cn0, yv0);
                yv1 = fmaf(h[n + 1], Cn1, yv1);
            }
            int t = c * 8 + s;
            int m = rev ? (Mm - 1 - t) : t;
            Y[(baseRow + m) * Ee + e] = yv0 + yv1;
        }
        if (more) {
            #pragma unroll
            for (int s = 0; s < 8; s++) { xb[s] = nx[s]; db[s] = nd[s]; }
            sBC[buf ^ 1][ls][ln] = nbc;
        }
        __syncthreads();
    }
}

// ---------------- gate multiply: writes bf16 (final GEMM A operand) --------------
__global__ void mul_kernel(const float4* __restrict__ a, const float4* __restrict__ b,
                           const float4* __restrict__ z, uint2* __restrict__ o, int n4)
{
    for (int i = blockIdx.x * blockDim.x + threadIdx.x; i < n4; i += gridDim.x * blockDim.x) {
        float4 A = a[i], Bv = b[i], Z = z[i];
        o[i] = make_uint2(packbf((A.x + Bv.x) * Z.x, (A.y + Bv.y) * Z.y),
                          packbf((A.z + Bv.z) * Z.z, (A.w + Bv.w) * Z.w));
    }
}

// ---------------- launch ----------------
extern "C" void kernel_launch(void* const* d_in, const int* in_sizes, int n_in,
                              void* d_out, int out_size)
{
    const float* t    = (const float*)d_in[0];
    const float* ln_g = (const float*)d_in[1];
    const float* ln_b = (const float*)d_in[2];
    const float* Wx   = (const float*)d_in[3];
    const float* bx   = (const float*)d_in[4];
    const float* Wz   = (const float*)d_in[5];
    const float* bz   = (const float*)d_in[6];
    const float* Wcf  = (const float*)d_in[7];
    const float* bcf  = (const float*)d_in[8];
    const float* Wcb  = (const float*)d_in[9];
    const float* bcb  = (const float*)d_in[10];
    const float* WBf  = (const float*)d_in[11];
    const float* bBf  = (const float*)d_in[12];
    const float* WCf  = (const float*)d_in[13];
    const float* bCf  = (const float*)d_in[14];
    const float* WDf  = (const float*)d_in[15];
    const float* bDf  = (const float*)d_in[16];
    const float* WBb  = (const float*)d_in[17];
    const float* bBb  = (const float*)d_in[18];
    const float* WCb  = (const float*)d_in[19];
    const float* bCb  = (const float*)d_in[20];
    const float* WDb  = (const float*)d_in[21];
    const float* bDb  = (const float*)d_in[22];
    const float* Abf  = (const float*)d_in[23];
    const float* Abb  = (const float*)d_in[24];
    const float* dbf  = (const float*)d_in[25];
    const float* dbb  = (const float*)d_in[26];
    const float* WT   = (const float*)d_in[27];
    const float* bT   = (const float*)d_in[28];
    float* out = (float*)d_out;

    void *p;
    cudaGetSymbolAddress(&p, g_xn_h);   __nv_bfloat16* xn_h  = (__nv_bfloat16*)p;
    cudaGetSymbolAddress(&p, g_xpj_h);  __nv_bfloat16* xpj_h = (__nv_bfloat16*)p;
    cudaGetSymbolAddress(&p, g_zs);     float* zs    = (float*)p;
    cudaGetSymbolAddress(&p, g_xpf);    float* xpf   = (float*)p;
    cudaGetSymbolAddress(&p, g_xpb);    float* xpb   = (float*)p;
    cudaGetSymbolAddress(&p, g_xpf_h);  __nv_bfloat16* xpf_h = (__nv_bfloat16*)p;
    cudaGetSymbolAddress(&p, g_xpb_h);  __nv_bfloat16* xpb_h = (__nv_bfloat16*)p;
    cudaGetSymbolAddress(&p, g_df);     float* df    = (float*)p;
    cudaGetSymbolAddress(&p, g_dbk);    float* dbk   = (float*)p;
    cudaGetSymbolAddress(&p, g_yf);     float* yf    = (float*)p;
    cudaGetSymbolAddress(&p, g_yb);     float* yb    = (float*)p;
    cudaGetSymbolAddress(&p, g_gate_h); __nv_bfloat16* gate_h = (__nv_bfloat16*)p;
    cudaGetSymbolAddress(&p, g_Bpf);    float* Bpf = (float*)p;
    cudaGetSymbolAddress(&p, g_Cpf);    float* Cpf = (float*)p;
    cudaGetSymbolAddress(&p, g_Bpb);    float* Bpb = (float*)p;
    cudaGetSymbolAddress(&p, g_Cpb);    float* Cpb = (float*)p;
    cudaGetSymbolAddress(&p, g_wcf_h);  __nv_bfloat16* wcf_h = (__nv_bfloat16*)p;
    cudaGetSymbolAddress(&p, g_wcb_h);  __nv_bfloat16* wcb_h = (__nv_bfloat16*)p;
    cudaGetSymbolAddress(&p, g_wx_h);   __nv_bfloat16* wx_h  = (__nv_bfloat16*)p;
    cudaGetSymbolAddress(&p, g_wz_h);   __nv_bfloat16* wz_h  = (__nv_bfloat16*)p;
    cudaGetSymbolAddress(&p, g_wdf_h);  __nv_bfloat16* wdf_h = (__nv_bfloat16*)p;
    cudaGetSymbolAddress(&p, g_wdb_h);  __nv_bfloat16* wdb_h = (__nv_bfloat16*)p;
    cudaGetSymbolAddress(&p, g_wt_h);   __nv_bfloat16* wt_h  = (__nv_bfloat16*)p;

    // 0. weight conversions (bf16) — tiny, one-time per launch
    cvt_kernel<<<(Ee*Dd/4 + 255)/256, 256>>>((const float4*)Wx,  (uint2*)wx_h,  Ee*Dd/4);
    cvt_kernel<<<(Ee*Dd/4 + 255)/256, 256>>>((const float4*)Wz,  (uint2*)wz_h,  Ee*Dd/4);
    cvt_kernel<<<(Ee*Ee/4 + 255)/256, 256>>>((const float4*)WDf, (uint2*)wdf_h, Ee*Ee/4);
    cvt_kernel<<<(Ee*Ee/4 + 255)/256, 256>>>((const float4*)WDb, (uint2*)wdb_h, Ee*Ee/4);
    cvt_kernel<<<(Dd*Ee/4 + 255)/256, 256>>>((const float4*)WT,  (uint2*)wt_h,  Dd*Ee/4);
    repack_conv<<<(Ee*Ee + 255)/256, 256>>>(Wcf, wcf_h);
    repack_conv<<<(Ee*Ee + 255)/256, 256>>>(Wcb, wcb_h);

    // 1. layernorm -> bf16
    ln_kernel<<<BMr, 256>>>(t, ln_g, ln_b, xn_h);

    // 2. x_proj (bf16 out) and silu(z) (f32 out)
    dim3 gEB(Ee/128, BMr/128);
    gemm_bf<0,1><<<gEB, 256>>>(xn_h, wx_h, bx, nullptr, nullptr, nullptr, xpj_h, Ee, Dd);
    gemm_bf<1,0><<<gEB, 256>>>(xn_h, wz_h, bz, nullptr, nullptr, zs, nullptr, Ee, Dd);

    // 3. convs (bias + silu fused, dual f32+bf16 output)
    conv_bf<<<gEB, 256>>>(xpj_h, wcf_h, bcf, xpf, xpf_h);
    conv_bf<<<gEB, 256>>>(xpj_h, wcb_h, bcb, xpb, xpb_h);

    // 4. B/C projections (f32 inputs)
    bc_kernel<<<BMr/256, 256>>>(xpf, WBf, bBf, WCf, bCf, Bpf, Cpf);
    bc_kernel<<<BMr/256, 256>>>(xpb, WBb, bBb, WCb, bCb, Bpb, Cpb);

    // 5. Delta (softplus, f32 out, bf16 A operand)
    gemm_bf<2,0><<<gEB, 256>>>(xpf_h, wdf_h, bDf, dbf, nullptr, df,  nullptr, Ee, Ee);
    gemm_bf<2,0><<<gEB, 256>>>(xpb_h, wdb_h, bDb, dbb, nullptr, dbk, nullptr, Ee, Ee);

    // 6. scans
    scan_kernel<<<dim3(Ee/256, Bb, 2), 256>>>(xpf, df, Bpf, Cpf, Abf, yf,
                                              xpb, dbk, Bpb, Cpb, Abb, yb);

    // 7. gate multiply -> bf16
    mul_kernel<<<2048, 256>>>((const float4*)yf, (const float4*)yb,
                              (const float4*)zs, (uint2*)gate_h,
                              (BMr * Ee) / 4);

    // 8. final projection + residual
    gemm_bf<0,0><<<dim3(Dd/128, BMr/128), 256>>>(gate_h, wt_h, bT, nullptr, t, out, nullptr, Dd, Ee);
}

// round 16
// speedup vs baseline: 1.3065x; 1.0119x over previous
#include <cuda_runtime.h>
#include <cuda_bf16.h>
#include <math.h>
#include <stdint.h>

#define Bb 4
#define Mm 4096
#define Dd 768
#define Ee 1536
#define Nn 16
#define KK 3
#define BMr (Bb*Mm)   // 16384 rows

// ---------------- scratch (static device globals; allocation-free) ----------------
__device__ __nv_bfloat16 g_xn_h [BMr*Dd];     // LN output (GEMM A operand)
__device__ __nv_bfloat16 g_xpj_h[BMr*Ee];     // x_proj (conv A operand)
__device__ float         g_zs   [BMr*Ee];     // silu(z) f32 (gate input)
__device__ float         g_xpf  [BMr*Ee];     // conv outputs f32 (bc + scan)
__device__ float         g_xpb  [BMr*Ee];
__device__ __nv_bfloat16 g_xpf_h[BMr*Ee];     // conv outputs bf16 (delta-GEMM A)
__device__ __nv_bfloat16 g_xpb_h[BMr*Ee];
__device__ float         g_df   [BMr*Ee];
__device__ float         g_dbk  [BMr*Ee];
__device__ float         g_yf   [BMr*Ee];
__device__ float         g_yb   [BMr*Ee];
__device__ __nv_bfloat16 g_gate_h[BMr*Ee];    // (yf+yb)*silu(z) bf16 (final GEMM A)
__device__ float g_Bpf[BMr*Nn], g_Cpf[BMr*Nn], g_Bpb[BMr*Nn], g_Cpb[BMr*Nn];
// bf16 weights
__device__ __nv_bfloat16 g_wcf_h[KK*Ee*Ee];   // conv weights repacked [k][o][i]
__device__ __nv_bfloat16 g_wcb_h[KK*Ee*Ee];
__device__ __nv_bfloat16 g_wx_h [Ee*Dd];
__device__ __nv_bfloat16 g_wz_h [Ee*Dd];
__device__ __nv_bfloat16 g_wdf_h[Ee*Ee];
__device__ __nv_bfloat16 g_wdb_h[Ee*Ee];
__device__ __nv_bfloat16 g_wt_h [Dd*Ee];

// ---------------- helpers ----------------
__device__ __forceinline__ float silu_f(float x)     { return x / (1.f + expf(-x)); }
__device__ __forceinline__ float softplus_f(float x) { return (x > 20.f) ? x : log1pf(expf(x)); }

__device__ __forceinline__ uint32_t packbf(float a, float b) {
    __nv_bfloat162 h = __floats2bfloat162_rn(a, b);   // low = a, high = b
    return *reinterpret_cast<uint32_t*>(&h);
}

__device__ __forceinline__ void mma_bf16(float* c, const uint32_t* a, const uint32_t* b) {
    asm volatile(
        "mma.sync.aligned.m16n8k16.row.col.f32.bf16.bf16.f32 "
        "{%0,%1,%2,%3}, {%4,%5,%6,%7}, {%8,%9}, {%0,%1,%2,%3};\n"
        : "+f"(c[0]), "+f"(c[1]), "+f"(c[2]), "+f"(c[3])
        : "r"(a[0]), "r"(a[1]), "r"(a[2]), "r"(a[3]),
          "r"(b[0]), "r"(b[1]));
}

// ---------------- f32 -> bf16 bulk convert (weights) ----------------
__global__ void cvt_kernel(const float4* __restrict__ in, uint2* __restrict__ out, int n4)
{
    int i = blockIdx.x * blockDim.x + threadIdx.x;
    if (i < n4) {
        float4 v = in[i];
        out[i] = make_uint2(packbf(v.x, v.y), packbf(v.z, v.w));
    }
}

// ---------------- conv weight repack + convert: w[o][i][k] -> out_bf16[k][o][i] ----
__global__ void repack_conv(const float* __restrict__ w, __nv_bfloat16* __restrict__ out)
{
    int idx = blockIdx.x * blockDim.x + threadIdx.x;
    if (idx >= Ee*Ee) return;
    int o = idx / Ee, i = idx % Ee;
    #pragma unroll
    for (int k = 0; k < KK; k++)
        out[(size_t)k*Ee*Ee + (size_t)o*Ee + i] = __float2bfloat16(w[((size_t)o*Ee + i)*KK + k]);
}

// ---------------- layernorm: one block per row of 768; bf16 output ----------------
__global__ void ln_kernel(const float* __restrict__ t, const float* __restrict__ g,
                          const float* __restrict__ b, __nv_bfloat16* __restrict__ xn)
{
    int row = blockIdx.x;
    int tid = threadIdx.x;
    const float* x = t + (size_t)row * Dd;
    float v0 = x[tid], v1 = x[tid + 256], v2 = x[tid + 512];
    float s  = v0 + v1 + v2;
    float sq = v0*v0 + v1*v1 + v2*v2;
    #pragma unroll
    for (int off = 16; off > 0; off >>= 1) {
        s  += __shfl_down_sync(0xffffffffu, s,  off);
        sq += __shfl_down_sync(0xffffffffu, sq, off);
    }
    __shared__ float red[16];
    int warp = tid >> 5, lane = tid & 31;
    if (lane == 0) { red[warp] = s; red[8 + warp] = sq; }
    __syncthreads();
    if (tid == 0) {
        float S = 0.f, Q = 0.f;
        #pragma unroll
        for (int w = 0; w < 8; w++) { S += red[w]; Q += red[8 + w]; }
        red[0] = S; red[8] = Q;
    }
    __syncthreads();
    float mu  = red[0] * (1.f / Dd);
    float var = red[8] * (1.f / Dd) - mu * mu;
    float inv = rsqrtf(var + 1e-5f);
    __nv_bfloat16* o = xn + (size_t)row * Dd;
    o[tid]       = __float2bfloat16((v0 - mu) * inv * g[tid]       + b[tid]);
    o[tid + 256] = __float2bfloat16((v1 - mu) * inv * g[tid + 256] + b[tid + 256]);
    o[tid + 512] = __float2bfloat16((v2 - mu) * inv * g[tid + 512] + b[tid + 512]);
}

// ================= bf16-everywhere tensor-core NT GEMM (R3 schedule) =============
// C[M,N] = A[M,K] @ W[N,K]^T + bias (+bias2) [ACT] (+resid)
// A, W bf16 in gmem. 128x128x16 tile, 256 threads, warp grid 4x2, 32x64/warp.
// __launch_bounds__(256,2): force regs<=128 so 2 CTAs co-reside per SM
// (smem 12.3KB is never the limiter) -> cross-CTA latency hiding.
// OUT: 0 = f32 only, 1 = bf16 only, 2 = both.
template<int ACT, int OUT>
__global__ void __launch_bounds__(256, 2)
gemm_bf(const __nv_bfloat16* __restrict__ A, const __nv_bfloat16* __restrict__ W,
        const float* __restrict__ bias, const float* __restrict__ bias2,
        const float* __restrict__ resid, float* __restrict__ C,
        __nv_bfloat16* __restrict__ Ch, int Ntot, int Ktot)
{
    __shared__ uint32_t As[128][12];
    __shared__ uint32_t Bs[128][12];
    int tid  = threadIdx.x;
    int brow = blockIdx.y * 128;
    int bcol = blockIdx.x * 128;
    int w  = tid >> 5, l = tid & 31;
    int rb = (w & 3) * 32;
    int cb = (w >> 2) * 64;
    int g  = l >> 2, tg = l & 3;
    int lr  = tid & 127;        // row 0..127
    int lhf = tid >> 7;         // k-half: 0 -> halves 0..7, 1 -> halves 8..15

    const __nv_bfloat16* Ap = A + (size_t)(brow + lr) * Ktot + lhf * 8;
    const __nv_bfloat16* Wp = W + (size_t)(bcol + lr) * Ktot + lhf * 8;

    float acc[2][8][4];
    #pragma unroll
    for (int i = 0; i < 2; i++)
        #pragma unroll
        for (int j = 0; j < 8; j++)
            #pragma unroll
            for (int q = 0; q < 4; q++) acc[i][j][q] = 0.f;

    uint4 pa = *(const uint4*)Ap;
    uint4 pw = *(const uint4*)Wp;

    int T = Ktot >> 4;
    for (int kt = 0; kt < T; ++kt) {
        __syncthreads();
        *(uint4*)&As[lr][lhf * 4] = pa;
        *(uint4*)&Bs[lr][lhf * 4] = pw;
        __syncthreads();
        if (kt + 1 < T) {
            pa = *(const uint4*)(Ap + (kt + 1) * 16);
            pw = *(const uint4*)(Wp + (kt + 1) * 16);
        }
        uint32_t af[2][4], bf[8][2];
        #pragma unroll
        for (int mt = 0; mt < 2; mt++) {
            int r = rb + mt * 16 + g;
            af[mt][0] = As[r    ][tg];
            af[mt][1] = As[r + 8][tg];
            af[mt][2] = As[r    ][tg + 4];
            af[mt][3] = As[r + 8][tg + 4];
        }
        #pragma unroll
        for (int nt = 0; nt < 8; nt++) {
            int n = cb + nt * 8 + g;
            bf[nt][0] = Bs[n][tg];
            bf[nt][1] = Bs[n][tg + 4];
        }
        #pragma unroll
        for (int mt = 0; mt < 2; mt++)
            #pragma unroll
            for (int nt = 0; nt < 8; nt++)
                mma_bf16(acc[mt][nt], af[mt], bf[nt]);
    }

    // epilogue
    #pragma unroll
    for (int mt = 0; mt < 2; mt++) {
        int r0 = brow + rb + mt * 16 + g;
        #pragma unroll
        for (int nt = 0; nt < 8; nt++) {
            int col = bcol + cb + nt * 8 + 2 * tg;
            float b0 = bias[col], b1 = bias[col + 1];
            if (bias2) { b0 += bias2[col]; b1 += bias2[col + 1]; }
            float v0 = acc[mt][nt][0] + b0;
            float v1 = acc[mt][nt][1] + b1;
            float v2 = acc[mt][nt][2] + b0;
            float v3 = acc[mt][nt][3] + b1;
            if (ACT == 1) { v0 = silu_f(v0); v1 = silu_f(v1); v2 = silu_f(v2); v3 = silu_f(v3); }
            if (ACT == 2) { v0 = softplus_f(v0); v1 = softplus_f(v1); v2 = softplus_f(v2); v3 = softplus_f(v3); }
            if (resid) {
                v0 += resid[(size_t)r0 * Ntot + col];
                v1 += resid[(size_t)r0 * Ntot + col + 1];
                v2 += resid[(size_t)(r0 + 8) * Ntot + col];
                v3 += resid[(size_t)(r0 + 8) * Ntot + col + 1];
            }
            if (OUT != 1) {
                *(float2*)&C[(size_t)r0 * Ntot + col]       = make_float2(v0, v1);
                *(float2*)&C[(size_t)(r0 + 8) * Ntot + col] = make_float2(v2, v3);
            }
            if (OUT != 0) {
                *(uint32_t*)&Ch[(size_t)r0 * Ntot + col]       = packbf(v0, v1);
                *(uint32_t*)&Ch[(size_t)(r0 + 8) * Ntot + col] = packbf(v2, v3);
            }
        }
    }
}

// ---------------- conv-as-GEMM (shifted A gather), bf16 operands ----------------
// Dual output: f32 (bc + scan) and bf16 (delta-GEMM A operand). Fused bias+silu.
__global__ void __launch_bounds__(256, 2)
conv_bf(const __nv_bfloat16* __restrict__ X, const __nv_bfloat16* __restrict__ Wp,
        const float* __restrict__ bias, float* __restrict__ C,
        __nv_bfloat16* __restrict__ Ch)
{
    __shared__ uint32_t As[128][12];
    __shared__ uint32_t Bs[128][12];
    int tid  = threadIdx.x;
    int brow = blockIdx.y * 128;
    int bcol = blockIdx.x * 128;
    int b_ = brow / Mm;
    int m0 = brow % Mm;
    int w  = tid >> 5, l = tid & 31;
    int rb = (w & 3) * 32;
    int cb = (w >> 2) * 64;
    int g  = l >> 2, tg = l & 3;
    int lr  = tid & 127;
    int lhf = tid >> 7;

    float acc[2][8][4];
    #pragma unroll
    for (int i = 0; i < 2; i++)
        #pragma unroll
        for (int j = 0; j < 8; j++)
            #pragma unroll
            for (int q = 0; q < 4; q++) acc[i][j][q] = 0.f;

    const int T = (KK * Ee) >> 4; // 288 ktiles
    uint4 pa, pw;

    auto fetch = [&](int kt) {
        int k0  = kt * 16;
        int seg = k0 / Ee;
        int e0  = k0 % Ee;
        int sh  = seg - 1;
        int mA = m0 + lr + sh;
        pa = (mA >= 0 && mA < Mm)
           ? *(const uint4*)(X + (size_t)(b_*Mm + mA)*Ee + e0 + lhf*8)
           : make_uint4(0u,0u,0u,0u);
        pw = *(const uint4*)(Wp + ((size_t)seg*Ee + bcol + lr)*Ee + e0 + lhf*8);
    };

    fetch(0);

    for (int kt = 0; kt < T; ++kt) {
        __syncthreads();
        *(uint4*)&As[lr][lhf * 4] = pa;
        *(uint4*)&Bs[lr][lhf * 4] = pw;
        __syncthreads();
        if (kt + 1 < T) fetch(kt + 1);
        uint32_t af[2][4], bf[8][2];
        #pragma unroll
        for (int mt = 0; mt < 2; mt++) {
            int r = rb + mt * 16 + g;
            af[mt][0] = As[r    ][tg];
            af[mt][1] = As[r + 8][tg];
            af[mt][2] = As[r    ][tg + 4];
            af[mt][3] = As[r + 8][tg + 4];
        }
        #pragma unroll
        for (int nt = 0; nt < 8; nt++) {
            int n = cb + nt * 8 + g;
            bf[nt][0] = Bs[n][tg];
            bf[nt][1] = Bs[n][tg + 4];
        }
        #pragma unroll
        for (int mt = 0; mt < 2; mt++)
            #pragma unroll
            for (int nt = 0; nt < 8; nt++)
                mma_bf16(acc[mt][nt], af[mt], bf[nt]);
    }

    #pragma unroll
    for (int mt = 0; mt < 2; mt++) {
        int r0 = brow + rb + mt * 16 + g;
        #pragma unroll
        for (int nt = 0; nt < 8; nt++) {
            int col = bcol + cb + nt * 8 + 2 * tg;
            float b0 = bias[col], b1 = bias[col + 1];
            float v0 = silu_f(acc[mt][nt][0] + b0);
            float v1 = silu_f(acc[mt][nt][1] + b1);
            float v2 = silu_f(acc[mt][nt][2] + b0);
            float v3 = silu_f(acc[mt][nt][3] + b1);
            *(float2*)&C[(size_t)r0 * Ee + col]       = make_float2(v0, v1);
            *(float2*)&C[(size_t)(r0 + 8) * Ee + col] = make_float2(v2, v3);
            *(uint32_t*)&Ch[(size_t)r0 * Ee + col]       = packbf(v0, v1);
            *(uint32_t*)&Ch[(size_t)(r0 + 8) * Ee + col] = packbf(v2, v3);
        }
    }
}

// ---------------- B/C projections: per-row 16+16 outputs (f32 inputs) ------------
__global__ void __launch_bounds__(256)
bc_kernel(const float* __restrict__ X,
          const float* __restrict__ WB, const float* __restrict__ bB,
          const float* __restrict__ WC, const float* __restrict__ bC,
          float* __restrict__ Bp, float* __restrict__ Cp)
{
    __shared__ float sWB[Nn][256];
    __shared__ float sWC[Nn][256];
    int tid = threadIdx.x;
    int row = blockIdx.x * 256 + tid;
    float accB[Nn], accC[Nn];
    #pragma unroll
    for (int n = 0; n < Nn; n++) { accB[n] = 0.f; accC[n] = 0.f; }

    for (int ec = 0; ec < Ee; ec += 256) {
        __syncthreads();
        #pragma unroll
        for (int q = 0; q < 4; q++) {
            int f4 = q * 256 + tid;
            int n  = f4 >> 6;
            int e4 = (f4 & 63) * 4;
            *(float4*)&sWB[n][e4] = *(const float4*)(WB + (size_t)n*Ee + ec + e4);
            *(float4*)&sWC[n][e4] = *(const float4*)(WC + (size_t)n*Ee + ec + e4);
        }
        __syncthreads();
        for (int e = 0; e < 256; e += 4) {
            float4 xv = *(const float4*)(X + (size_t)row*Ee + ec + e);
            #pragma unroll
            for (int n = 0; n < Nn; n++) {
                float4 wb = *(const float4*)&sWB[n][e];
                float4 wc = *(const float4*)&sWC[n][e];
                accB[n] = fmaf(xv.x, wb.x, accB[n]);
                accB[n] = fmaf(xv.y, wb.y, accB[n]);
                accB[n] = fmaf(xv.z, wb.z, accB[n]);
                accB[n] = fmaf(xv.w, wb.w, accB[n]);
                accC[n] = fmaf(xv.x, wc.x, accC[n]);
                accC[n] = fmaf(xv.y, wc.y, accC[n]);
                accC[n] = fmaf(xv.z, wc.z, accC[n]);
                accC[n] = fmaf(xv.w, wc.w, accC[n]);
            }
        }
    }
    #pragma unroll
    for (int n = 0; n < Nn; n++) {
        Bp[(size_t)row*Nn + n] = accB[n] + bB[n];
        Cp[(size_t)row*Nn + n] = accC[n] + bC[n];
    }
}

// ---------------- scan: both directions in one launch; thread = one e ----------------
__global__ void __launch_bounds__(256)
scan_kernel(const float* __restrict__ Xf, const float* __restrict__ Df,
            const float* __restrict__ Bpf, const float* __restrict__ Cpf,
            const float* __restrict__ Af,  float* __restrict__ Yf,
            const float* __restrict__ Xb, const float* __restrict__ Db,
            const float* __restrict__ Bpb, const float* __restrict__ Cpb,
            const float* __restrict__ Ab,  float* __restrict__ Yb)
{
    int dir = blockIdx.z;
    const float *X, *Dl, *Bp, *Cp, *A;
    float* Y;
    if (dir == 0) { X = Xf; Dl = Df; Bp = Bpf; Cp = Cpf; A = Af; Y = Yf; }
    else          { X = Xb; Dl = Db; Bp = Bpb; Cp = Cpb; A = Ab; Y = Yb; }
    bool rev = (dir == 1);

    int b_  = blockIdx.y;
    int tid = threadIdx.x;
    int e   = blockIdx.x * 256 + tid;
    size_t baseRow = (size_t)b_ * Mm;

    float a[Nn];
    #pragma unroll
    for (int q = 0; q < 4; q++) {
        float4 av = *(const float4*)(A + (size_t)e*Nn + q*4);
        a[q*4+0] = av.x; a[q*4+1] = av.y; a[q*4+2] = av.z; a[q*4+3] = av.w;
    }
    float h[Nn];
    #pragma unroll
    for (int n = 0; n < Nn; n++) h[n] = 0.f;

    __shared__ float sBC[2][8][32];
    int ls = tid >> 5;
    int ln = tid & 31;

    float xb[8], db[8];
    #pragma unroll
    for (int s = 0; s < 8; s++) {
        int m = rev ? (Mm - 1 - s) : s;
        size_t idx = (baseRow + m) * Ee + e;
        xb[s] = X[idx]; db[s] = Dl[idx];
    }
    {
        int m = rev ? (Mm - 1 - ls) : ls;
        sBC[0][ls][ln] = (ln < Nn) ? Bp[(baseRow + m)*Nn + ln]
                                   : Cp[(baseRow + m)*Nn + (ln - Nn)];
    }
    __syncthreads();

    const int NCH = Mm / 8;
    for (int c = 0; c < NCH; ++c) {
        int buf = c & 1;
        float nx[8], nd[8], nbc = 0.f;
        bool more = (c + 1 < NCH);
        if (more) {
            #pragma unroll
            for (int s = 0; s < 8; s++) {
                int t = (c + 1) * 8 + s;
                int m = rev ? (Mm - 1 - t) : t;
                size_t idx = (baseRow + m) * Ee + e;
                nx[s] = X[idx]; nd[s] = Dl[idx];
            }
            int t = (c + 1) * 8 + ls;
            int m = rev ? (Mm - 1 - t) : t;
            nbc = (ln < Nn) ? Bp[(baseRow + m)*Nn + ln]
                            : Cp[(baseRow + m)*Nn + (ln - Nn)];
        }
        #pragma unroll
        for (int s = 0; s < 8; s++) {
            float dv = db[s], xv = xb[s];
            float dx = dv * xv;
            float yv0 = 0.f, yv1 = 0.f;
            #pragma unroll
            for (int n = 0; n < Nn; n += 2) {
                float Bn0 = sBC[buf][s][n];
                float Cn0 = sBC[buf][s][Nn + n];
                float Bn1 = sBC[buf][s][n + 1];
                float Cn1 = sBC[buf][s][Nn + n + 1];
                h[n]     = fmaf(dv * a[n],     h[n],     dx * Bn0);
                h[n + 1] = fmaf(dv * a[n + 1], h[n + 1], dx * Bn1);
                yv0 = fmaf(h[n],     Cn0, yv0);
                yv1 = fmaf(h[n + 1], Cn1, yv1);
            }
            int t = c * 8 + s;
            int m = rev ? (Mm - 1 - t) : t;
            Y[(baseRow + m) * Ee + e] = yv0 + yv1;
        }
        if (more) {
            #pragma unroll
            for (int s = 0; s < 8; s++) { xb[s] = nx[s]; db[s] = nd[s]; }
            sBC[buf ^ 1][ls][ln] = nbc;
        }
        __syncthreads();
    }
}

// ---------------- gate multiply: writes bf16 (final GEMM A operand) --------------
__global__ void mul_kernel(const float4* __restrict__ a, const float4* __restrict__ b,
                           const float4* __restrict__ z, uint2* __restrict__ o, int n4)
{
    for (int i = blockIdx.x * blockDim.x + threadIdx.x; i < n4; i += gridDim.x * blockDim.x) {
        float4 A = a[i], Bv = b[i], Z = z[i];
        o[i] = make_uint2(packbf((A.x + Bv.x) * Z.x, (A.y + Bv.y) * Z.y),
                          packbf((A.z + Bv.z) * Z.z, (A.w + Bv.w) * Z.w));
    }
}

// ---------------- launch ----------------
extern "C" void kernel_launch(void* const* d_in, const int* in_sizes, int n_in,
                              void* d_out, int out_size)
{
    const float* t    = (const float*)d_in[0];
    const float* ln_g = (const float*)d_in[1];
    const float* ln_b = (const float*)d_in[2];
    const float* Wx   = (const float*)d_in[3];
    const float* bx   = (const float*)d_in[4];
    const float* Wz   = (const float*)d_in[5];
    const float* bz   = (const float*)d_in[6];
    const float* Wcf  = (const float*)d_in[7];
    const float* bcf  = (const float*)d_in[8];
    const float* Wcb  = (const float*)d_in[9];
    const float* bcb  = (const float*)d_in[10];
    const float* WBf  = (const float*)d_in[11];
    const float* bBf  = (const float*)d_in[12];
    const float* WCf  = (const float*)d_in[13];
    const float* bCf  = (const float*)d_in[14];
    const float* WDf  = (const float*)d_in[15];
    const float* bDf  = (const float*)d_in[16];
    const float* WBb  = (const float*)d_in[17];
    const float* bBb  = (const float*)d_in[18];
    const float* WCb  = (const float*)d_in[19];
    const float* bCb  = (const float*)d_in[20];
    const float* WDb  = (const float*)d_in[21];
    const float* bDb  = (const float*)d_in[22];
    const float* Abf  = (const float*)d_in[23];
    const float* Abb  = (const float*)d_in[24];
    const float* dbf  = (const float*)d_in[25];
    const float* dbb  = (const float*)d_in[26];
    const float* WT   = (const float*)d_in[27];
    const float* bT   = (const float*)d_in[28];
    float* out = (float*)d_out;

    void *p;
    cudaGetSymbolAddress(&p, g_xn_h);   __nv_bfloat16* xn_h  = (__nv_bfloat16*)p;
    cudaGetSymbolAddress(&p, g_xpj_h);  __nv_bfloat16* xpj_h = (__nv_bfloat16*)p;
    cudaGetSymbolAddress(&p, g_zs);     float* zs    = (float*)p;
    cudaGetSymbolAddress(&p, g_xpf);    float* xpf   = (float*)p;
    cudaGetSymbolAddress(&p, g_xpb);    float* xpb   = (float*)p;
    cudaGetSymbolAddress(&p, g_xpf_h);  __nv_bfloat16* xpf_h = (__nv_bfloat16*)p;
    cudaGetSymbolAddress(&p, g_xpb_h);  __nv_bfloat16* xpb_h = (__nv_bfloat16*)p;
    cudaGetSymbolAddress(&p, g_df);     float* df    = (float*)p;
    cudaGetSymbolAddress(&p, g_dbk);    float* dbk   = (float*)p;
    cudaGetSymbolAddress(&p, g_yf);     float* yf    = (float*)p;
    cudaGetSymbolAddress(&p, g_yb);     float* yb    = (float*)p;
    cudaGetSymbolAddress(&p, g_gate_h); __nv_bfloat16* gate_h = (__nv_bfloat16*)p;
    cudaGetSymbolAddress(&p, g_Bpf);    float* Bpf = (float*)p;
    cudaGetSymbolAddress(&p, g_Cpf);    float* Cpf = (float*)p;
    cudaGetSymbolAddress(&p, g_Bpb);    float* Bpb = (float*)p;
    cudaGetSymbolAddress(&p, g_Cpb);    float* Cpb = (float*)p;
    cudaGetSymbolAddress(&p, g_wcf_h);  __nv_bfloat16* wcf_h = (__nv_bfloat16*)p;
    cudaGetSymbolAddress(&p, g_wcb_h);  __nv_bfloat16* wcb_h = (__nv_bfloat16*)p;
    cudaGetSymbolAddress(&p, g_wx_h);   __nv_bfloat16* wx_h  = (__nv_bfloat16*)p;
    cudaGetSymbolAddress(&p, g_wz_h);   __nv_bfloat16* wz_h  = (__nv_bfloat16*)p;
    cudaGetSymbolAddress(&p, g_wdf_h);  __nv_bfloat16* wdf_h = (__nv_bfloat16*)p;
    cudaGetSymbolAddress(&p, g_wdb_h);  __nv_bfloat16* wdb_h = (__nv_bfloat16*)p;
    cudaGetSymbolAddress(&p, g_wt_h);   __nv_bfloat16* wt_h  = (__nv_bfloat16*)p;

    // 0. weight conversions (bf16) — tiny, one-time per launch
    cvt_kernel<<<(Ee*Dd/4 + 255)/256, 256>>>((const float4*)Wx,  (uint2*)wx_h,  Ee*Dd/4);
    cvt_kernel<<<(Ee*Dd/4 + 255)/256, 256>>>((const float4*)Wz,  (uint2*)wz_h,  Ee*Dd/4);
    cvt_kernel<<<(Ee*Ee/4 + 255)/256, 256>>>((const float4*)WDf, (uint2*)wdf_h, Ee*Ee/4);
    cvt_kernel<<<(Ee*Ee/4 + 255)/256, 256>>>((const float4*)WDb, (uint2*)wdb_h, Ee*Ee/4);
    cvt_kernel<<<(Dd*Ee/4 + 255)/256, 256>>>((const float4*)WT,  (uint2*)wt_h,  Dd*Ee/4);
    repack_conv<<<(Ee*Ee + 255)/256, 256>>>(Wcf, wcf_h);
    repack_conv<<<(Ee*Ee + 255)/256, 256>>>(Wcb, wcb_h);

    // 1. layernorm -> bf16
    ln_kernel<<<BMr, 256>>>(t, ln_g, ln_b, xn_h);

    // 2. x_proj (bf16 out) and silu(z) (f32 out)
    dim3 gEB(Ee/128, BMr/128);
    gemm_bf<0,1><<<gEB, 256>>>(xn_h, wx_h, bx, nullptr, nullptr, nullptr, xpj_h, Ee, Dd);
    gemm_bf<1,0><<<gEB, 256>>>(xn_h, wz_h, bz, nullptr, nullptr, zs, nullptr, Ee, Dd);

    // 3. convs (bias + silu fused, dual f32+bf16 output)
    conv_bf<<<gEB, 256>>>(xpj_h, wcf_h, bcf, xpf, xpf_h);
    conv_bf<<<gEB, 256>>>(xpj_h, wcb_h, bcb, xpb, xpb_h);

    // 4. B/C projections (f32 inputs)
    bc_kernel<<<BMr/256, 256>>>(xpf, WBf, bBf, WCf, bCf, Bpf, Cpf);
    bc_kernel<<<BMr/256, 256>>>(xpb, WBb, bBb, WCb, bCb, Bpb, Cpb);

    // 5. Delta (softplus, f32 out, bf16 A operand)
    gemm_bf<2,0><<<gEB, 256>>>(xpf_h, wdf_h, bDf, dbf, nullptr, df,  nullptr, Ee, Ee);
    gemm_bf<2,0><<<gEB, 256>>>(xpb_h, wdb_h, bDb, dbb, nullptr, dbk, nullptr, Ee, Ee);

    // 6. scans
    scan_kernel<<<dim3(Ee/256, Bb, 2), 256>>>(xpf, df, Bpf, Cpf, Abf, yf,
                                              xpb, dbk, Bpb, Cpb, Abb, yb);

    // 7. gate multiply -> bf16
    mul_kernel<<<2048, 256>>>((const float4*)yf, (const float4*)yb,
                              (const float4*)zs, (uint2*)gate_h,
                              (BMr * Ee) / 4);

    // 8. final projection + residual
    gemm_bf<0,0><<<dim3(Dd/128, BMr/128), 256>>>(gate_h, wt_h, bT, nullptr, t, out, nullptr, Dd, Ee);
}

// round 17
// speedup vs baseline: 1.3105x; 1.0031x over previous
#include <cuda_runtime.h>
#include <cuda_bf16.h>
#include <math.h>
#include <stdint.h>

#define Bb 4
#define Mm 4096
#define Dd 768
#define Ee 1536
#define Nn 16
#define KK 3
#define BMr (Bb*Mm)   // 16384 rows

// ---------------- scratch (static device globals; allocation-free) ----------------
__device__ __nv_bfloat16 g_xn_h [BMr*Dd];     // LN output (GEMM A operand)
__device__ __nv_bfloat16 g_xpj_h[BMr*Ee];     // x_proj (conv A operand)
__device__ float         g_zs   [BMr*Ee];     // silu(z) f32 (gate input)
__device__ float         g_xpf  [BMr*Ee];     // conv outputs f32 (bc + scan)
__device__ float         g_xpb  [BMr*Ee];
__device__ __nv_bfloat16 g_xpf_h[BMr*Ee];     // conv outputs bf16 (delta-GEMM A)
__device__ __nv_bfloat16 g_xpb_h[BMr*Ee];
__device__ float         g_df   [BMr*Ee];
__device__ float         g_dbk  [BMr*Ee];
__device__ float         g_yf   [BMr*Ee];
__device__ float         g_yb   [BMr*Ee];
__device__ __nv_bfloat16 g_gate_h[BMr*Ee];    // (yf+yb)*silu(z) bf16 (final GEMM A)
__device__ float g_Bpf[BMr*Nn], g_Cpf[BMr*Nn], g_Bpb[BMr*Nn], g_Cpb[BMr*Nn];
// bf16 weights
__device__ __nv_bfloat16 g_wcf_h[KK*Ee*Ee];   // conv weights repacked [k][o][i]
__device__ __nv_bfloat16 g_wcb_h[KK*Ee*Ee];
__device__ __nv_bfloat16 g_wx_h [Ee*Dd];
__device__ __nv_bfloat16 g_wz_h [Ee*Dd];
__device__ __nv_bfloat16 g_wdf_h[Ee*Ee];
__device__ __nv_bfloat16 g_wdb_h[Ee*Ee];
__device__ __nv_bfloat16 g_wt_h [Dd*Ee];

// ---------------- helpers ----------------
__device__ __forceinline__ float silu_f(float x)     { return x / (1.f + expf(-x)); }
__device__ __forceinline__ float softplus_f(float x) { return (x > 20.f) ? x : log1pf(expf(x)); }

__device__ __forceinline__ uint32_t packbf(float a, float b) {
    __nv_bfloat162 h = __floats2bfloat162_rn(a, b);   // low = a, high = b
    return *reinterpret_cast<uint32_t*>(&h);
}

__device__ __forceinline__ void mma_bf16(float* c, const uint32_t* a, const uint32_t* b) {
    asm volatile(
        "mma.sync.aligned.m16n8k16.row.col.f32.bf16.bf16.f32 "
        "{%0,%1,%2,%3}, {%4,%5,%6,%7}, {%8,%9}, {%0,%1,%2,%3};\n"
        : "+f"(c[0]), "+f"(c[1]), "+f"(c[2]), "+f"(c[3])
        : "r"(a[0]), "r"(a[1]), "r"(a[2]), "r"(a[3]),
          "r"(b[0]), "r"(b[1]));
}

// ---------------- f32 -> bf16 bulk convert (weights) ----------------
__global__ void cvt_kernel(const float4* __restrict__ in, uint2* __restrict__ out, int n4)
{
    int i = blockIdx.x * blockDim.x + threadIdx.x;
    if (i < n4) {
        float4 v = in[i];
        out[i] = make_uint2(packbf(v.x, v.y), packbf(v.z, v.w));
    }
}

// ---------------- conv weight repack + convert: w[o][i][k] -> out_bf16[k][o][i] ----
__global__ void repack_conv(const float* __restrict__ w, __nv_bfloat16* __restrict__ out)
{
    int idx = blockIdx.x * blockDim.x + threadIdx.x;
    if (idx >= Ee*Ee) return;
    int o = idx / Ee, i = idx % Ee;
    #pragma unroll
    for (int k = 0; k < KK; k++)
        out[(size_t)k*Ee*Ee + (size_t)o*Ee + i] = __float2bfloat16(w[((size_t)o*Ee + i)*KK + k]);
}

// ---------------- layernorm: one block per row of 768; bf16 output ----------------
__global__ void ln_kernel(const float* __restrict__ t, const float* __restrict__ g,
                          const float* __restrict__ b, __nv_bfloat16* __restrict__ xn)
{
    int row = blockIdx.x;
    int tid = threadIdx.x;
    const float* x = t + (size_t)row * Dd;
    float v0 = x[tid], v1 = x[tid + 256], v2 = x[tid + 512];
    float s  = v0 + v1 + v2;
    float sq = v0*v0 + v1*v1 + v2*v2;
    #pragma unroll
    for (int off = 16; off > 0; off >>= 1) {
        s  += __shfl_down_sync(0xffffffffu, s,  off);
        sq += __shfl_down_sync(0xffffffffu, sq, off);
    }
    __shared__ float red[16];
    int warp = tid >> 5, lane = tid & 31;
    if (lane == 0) { red[warp] = s; red[8 + warp] = sq; }
    __syncthreads();
    if (tid == 0) {
        float S = 0.f, Q = 0.f;
        #pragma unroll
        for (int w = 0; w < 8; w++) { S += red[w]; Q += red[8 + w]; }
        red[0] = S; red[8] = Q;
    }
    __syncthreads();
    float mu  = red[0] * (1.f / Dd);
    float var = red[8] * (1.f / Dd) - mu * mu;
    float inv = rsqrtf(var + 1e-5f);
    __nv_bfloat16* o = xn + (size_t)row * Dd;
    o[tid]       = __float2bfloat16((v0 - mu) * inv * g[tid]       + b[tid]);
    o[tid + 256] = __float2bfloat16((v1 - mu) * inv * g[tid + 256] + b[tid + 256]);
    o[tid + 512] = __float2bfloat16((v2 - mu) * inv * g[tid + 512] + b[tid + 512]);
}

// ================= bf16 tensor-core NT GEMM, K=32 tiles =================
// C[M,N] = A[M,K] @ W[N,K]^T + bias (+bias2) [ACT] (+resid)
// 128x128x32 tile, 256 threads, warp grid 4x2, 32x64/warp.
// smem [128][20] words (16 used + 4 pad), single-buffered, 2 syncs per 32-K tile:
// half the barriers of the K=16 schedule, 2x mma work (32 mma/warp) per window.
// Loader: lr=tid&127 row, lhf=tid>>7 k-half; 2x LDG.128 + 2x STS.128 per operand.
// OUT: 0 = f32 only, 1 = bf16 only, 2 = both.
template<int ACT, int OUT>
__global__ void __launch_bounds__(256, 2)
gemm_bf(const __nv_bfloat16* __restrict__ A, const __nv_bfloat16* __restrict__ W,
        const float* __restrict__ bias, const float* __restrict__ bias2,
        const float* __restrict__ resid, float* __restrict__ C,
        __nv_bfloat16* __restrict__ Ch, int Ntot, int Ktot)
{
    __shared__ uint32_t As[128][20];
    __shared__ uint32_t Bs[128][20];
    int tid  = threadIdx.x;
    int brow = blockIdx.y * 128;
    int bcol = blockIdx.x * 128;
    int w  = tid >> 5, l = tid & 31;
    int rb = (w & 3) * 32;
    int cb = (w >> 2) * 64;
    int g  = l >> 2, tg = l & 3;
    int lr  = tid & 127;        // row 0..127
    int lhf = tid >> 7;         // k-half: 0 -> halves 0..15, 1 -> halves 16..31

    const __nv_bfloat16* Ap = A + (size_t)(brow + lr) * Ktot + lhf * 16;
    const __nv_bfloat16* Wp = W + (size_t)(bcol + lr) * Ktot + lhf * 16;

    float acc[2][8][4];
    #pragma unroll
    for (int i = 0; i < 2; i++)
        #pragma unroll
        for (int j = 0; j < 8; j++)
            #pragma unroll
            for (int q = 0; q < 4; q++) acc[i][j][q] = 0.f;

    uint4 pa0 = *(const uint4*)Ap;
    uint4 pa1 = *(const uint4*)(Ap + 8);
    uint4 pw0 = *(const uint4*)Wp;
    uint4 pw1 = *(const uint4*)(Wp + 8);

    int T = Ktot >> 5; // 32-K tiles
    for (int kt = 0; kt < T; ++kt) {
        __syncthreads();
        *(uint4*)&As[lr][lhf * 8]     = pa0;
        *(uint4*)&As[lr][lhf * 8 + 4] = pa1;
        *(uint4*)&Bs[lr][lhf * 8]     = pw0;
        *(uint4*)&Bs[lr][lhf * 8 + 4] = pw1;
        __syncthreads();
        if (kt + 1 < T) {
            int k0 = (kt + 1) * 32;
            pa0 = *(const uint4*)(Ap + k0);
            pa1 = *(const uint4*)(Ap + k0 + 8);
            pw0 = *(const uint4*)(Wp + k0);
            pw1 = *(const uint4*)(Wp + k0 + 8);
        }
        #pragma unroll
        for (int kk = 0; kk < 2; kk++) {        // two k16 chunks per tile
            uint32_t af[2][4], bf[8][2];
            #pragma unroll
            for (int mt = 0; mt < 2; mt++) {
                int r = rb + mt * 16 + g;
                af[mt][0] = As[r    ][kk * 8 + tg];
                af[mt][1] = As[r + 8][kk * 8 + tg];
                af[mt][2] = As[r    ][kk * 8 + tg + 4];
                af[mt][3] = As[r + 8][kk * 8 + tg + 4];
            }
            #pragma unroll
            for (int nt = 0; nt < 8; nt++) {
                int n = cb + nt * 8 + g;
                bf[nt][0] = Bs[n][kk * 8 + tg];
                bf[nt][1] = Bs[n][kk * 8 + tg + 4];
            }
            #pragma unroll
            for (int mt = 0; mt < 2; mt++)
                #pragma unroll
                for (int nt = 0; nt < 8; nt++)
                    mma_bf16(acc[mt][nt], af[mt], bf[nt]);
        }
    }

    // epilogue
    #pragma unroll
    for (int mt = 0; mt < 2; mt++) {
        int r0 = brow + rb + mt * 16 + g;
        #pragma unroll
        for (int nt = 0; nt < 8; nt++) {
            int col = bcol + cb + nt * 8 + 2 * tg;
            float b0 = bias[col], b1 = bias[col + 1];
            if (bias2) { b0 += bias2[col]; b1 += bias2[col + 1]; }
            float v0 = acc[mt][nt][0] + b0;
            float v1 = acc[mt][nt][1] + b1;
            float v2 = acc[mt][nt][2] + b0;
            float v3 = acc[mt][nt][3] + b1;
            if (ACT == 1) { v0 = silu_f(v0); v1 = silu_f(v1); v2 = silu_f(v2); v3 = silu_f(v3); }
            if (ACT == 2) { v0 = softplus_f(v0); v1 = softplus_f(v1); v2 = softplus_f(v2); v3 = softplus_f(v3); }
            if (resid) {
                v0 += resid[(size_t)r0 * Ntot + col];
                v1 += resid[(size_t)r0 * Ntot + col + 1];
                v2 += resid[(size_t)(r0 + 8) * Ntot + col];
                v3 += resid[(size_t)(r0 + 8) * Ntot + col + 1];
            }
            if (OUT != 1) {
                *(float2*)&C[(size_t)r0 * Ntot + col]       = make_float2(v0, v1);
                *(float2*)&C[(size_t)(r0 + 8) * Ntot + col] = make_float2(v2, v3);
            }
            if (OUT != 0) {
                *(uint32_t*)&Ch[(size_t)r0 * Ntot + col]       = packbf(v0, v1);
                *(uint32_t*)&Ch[(size_t)(r0 + 8) * Ntot + col] = packbf(v2, v3);
            }
        }
    }
}

// ---------------- conv-as-GEMM (shifted A gather), bf16, K=32 tiles --------------
// Dual output: f32 (bc + scan) and bf16 (delta-GEMM A operand). Fused bias+silu.
// Ee % 32 == 0 so a 32-K tile never straddles a kernel-tap segment boundary.
__global__ void __launch_bounds__(256, 2)
conv_bf(const __nv_bfloat16* __restrict__ X, const __nv_bfloat16* __restrict__ Wp,
        const float* __restrict__ bias, float* __restrict__ C,
        __nv_bfloat16* __restrict__ Ch)
{
    __shared__ uint32_t As[128][20];
    __shared__ uint32_t Bs[128][20];
    int tid  = threadIdx.x;
    int brow = blockIdx.y * 128;
    int bcol = blockIdx.x * 128;
    int b_ = brow / Mm;
    int m0 = brow % Mm;
    int w  = tid >> 5, l = tid & 31;
    int rb = (w & 3) * 32;
    int cb = (w >> 2) * 64;
    int g  = l >> 2, tg = l & 3;
    int lr  = tid & 127;
    int lhf = tid >> 7;

    float acc[2][8][4];
    #pragma unroll
    for (int i = 0; i < 2; i++)
        #pragma unroll
        for (int j = 0; j < 8; j++)
            #pragma unroll
            for (int q = 0; q < 4; q++) acc[i][j][q] = 0.f;

    const int T = (KK * Ee) >> 5; // 144 tiles
    uint4 pa0, pa1, pw0, pw1;

    auto fetch = [&](int kt) {
        int k0  = kt * 32;
        int seg = k0 / Ee;
        int e0  = k0 % Ee;
        int sh  = seg - 1;
        int mA = m0 + lr + sh;
        if (mA >= 0 && mA < Mm) {
            const __nv_bfloat16* ap = X + (size_t)(b_*Mm + mA)*Ee + e0 + lhf*16;
            pa0 = *(const uint4*)ap;
            pa1 = *(const uint4*)(ap + 8);
        } else {
            pa0 = make_uint4(0u,0u,0u,0u);
            pa1 = make_uint4(0u,0u,0u,0u);
        }
        const __nv_bfloat16* wp = Wp + ((size_t)seg*Ee + bcol + lr)*Ee + e0 + lhf*16;
        pw0 = *(const uint4*)wp;
        pw1 = *(const uint4*)(wp + 8);
    };

    fetch(0);

    for (int kt = 0; kt < T; ++kt) {
        __syncthreads();
        *(uint4*)&As[lr][lhf * 8]     = pa0;
        *(uint4*)&As[lr][lhf * 8 + 4] = pa1;
        *(uint4*)&Bs[lr][lhf * 8]     = pw0;
        *(uint4*)&Bs[lr][lhf * 8 + 4] = pw1;
        __syncthreads();
        if (kt + 1 < T) fetch(kt + 1);
        #pragma unroll
        for (int kk = 0; kk < 2; kk++) {
            uint32_t af[2][4], bf[8][2];
            #pragma unroll
            for (int mt = 0; mt < 2; mt++) {
                int r = rb + mt * 16 + g;
                af[mt][0] = As[r    ][kk * 8 + tg];
                af[mt][1] = As[r + 8][kk * 8 + tg];
                af[mt][2] = As[r    ][kk * 8 + tg + 4];
                af[mt][3] = As[r + 8][kk * 8 + tg + 4];
            }
            #pragma unroll
            for (int nt = 0; nt < 8; nt++) {
                int n = cb + nt * 8 + g;
                bf[nt][0] = Bs[n][kk * 8 + tg];
                bf[nt][1] = Bs[n][kk * 8 + tg + 4];
            }
            #pragma unroll
            for (int mt = 0; mt < 2; mt++)
                #pragma unroll
                for (int nt = 0; nt < 8; nt++)
                    mma_bf16(acc[mt][nt], af[mt], bf[nt]);
        }
    }

    #pragma unroll
    for (int mt = 0; mt < 2; mt++) {
        int r0 = brow + rb + mt * 16 + g;
        #pragma unroll
        for (int nt = 0; nt < 8; nt++) {
            int col = bcol + cb + nt * 8 + 2 * tg;
            float b0 = bias[col], b1 = bias[col + 1];
            float v0 = silu_f(acc[mt][nt][0] + b0);
            float v1 = silu_f(acc[mt][nt][1] + b1);
            float v2 = silu_f(acc[mt][nt][2] + b0);
            float v3 = silu_f(acc[mt][nt][3] + b1);
            *(float2*)&C[(size_t)r0 * Ee + col]       = make_float2(v0, v1);
            *(float2*)&C[(size_t)(r0 + 8) * Ee + col] = make_float2(v2, v3);
            *(uint32_t*)&Ch[(size_t)r0 * Ee + col]       = packbf(v0, v1);
            *(uint32_t*)&Ch[(size_t)(r0 + 8) * Ee + col] = packbf(v2, v3);
        }
    }
}

// ---------------- B/C projections: per-row 16+16 outputs (f32 inputs) ------------
__global__ void __launch_bounds__(256)
bc_kernel(const float* __restrict__ X,
          const float* __restrict__ WB, const float* __restrict__ bB,
          const float* __restrict__ WC, const float* __restrict__ bC,
          float* __restrict__ Bp, float* __restrict__ Cp)
{
    __shared__ float sWB[Nn][256];
    __shared__ float sWC[Nn][256];
    int tid = threadIdx.x;
    int row = blockIdx.x * 256 + tid;
    float accB[Nn], accC[Nn];
    #pragma unroll
    for (int n = 0; n < Nn; n++) { accB[n] = 0.f; accC[n] = 0.f; }

    for (int ec = 0; ec < Ee; ec += 256) {
        __syncthreads();
        #pragma unroll
        for (int q = 0; q < 4; q++) {
            int f4 = q * 256 + tid;
            int n  = f4 >> 6;
            int e4 = (f4 & 63) * 4;
            *(float4*)&sWB[n][e4] = *(const float4*)(WB + (size_t)n*Ee + ec + e4);
            *(float4*)&sWC[n][e4] = *(const float4*)(WC + (size_t)n*Ee + ec + e4);
        }
        __syncthreads();
        for (int e = 0; e < 256; e += 4) {
            float4 xv = *(const float4*)(X + (size_t)row*Ee + ec + e);
            #pragma unroll
            for (int n = 0; n < Nn; n++) {
                float4 wb = *(const float4*)&sWB[n][e];
                float4 wc = *(const float4*)&sWC[n][e];
                accB[n] = fmaf(xv.x, wb.x, accB[n]);
                accB[n] = fmaf(xv.y, wb.y, accB[n]);
                accB[n] = fmaf(xv.z, wb.z, accB[n]);
                accB[n] = fmaf(xv.w, wb.w, accB[n]);
                accC[n] = fmaf(xv.x, wc.x, accC[n]);
                accC[n] = fmaf(xv.y, wc.y, accC[n]);
                accC[n] = fmaf(xv.z, wc.z, accC[n]);
                accC[n] = fmaf(xv.w, wc.w, accC[n]);
            }
        }
    }
    #pragma unroll
    for (int n = 0; n < Nn; n++) {
        Bp[(size_t)row*Nn + n] = accB[n] + bB[n];
        Cp[(size_t)row*Nn + n] = accC[n] + bC[n];
    }
}

// ---------------- scan: both directions in one launch; thread = one e ----------------
__global__ void __launch_bounds__(256)
scan_kernel(const float* __restrict__ Xf, const float* __restrict__ Df,
            const float* __restrict__ Bpf, const float* __restrict__ Cpf,
            const float* __restrict__ Af,  float* __restrict__ Yf,
            const float* __restrict__ Xb, const float* __restrict__ Db,
            const float* __restrict__ Bpb, const float* __restrict__ Cpb,
            const float* __restrict__ Ab,  float* __restrict__ Yb)
{
    int dir = blockIdx.z;
    const float *X, *Dl, *Bp, *Cp, *A;
    float* Y;
    if (dir == 0) { X = Xf; Dl = Df; Bp = Bpf; Cp = Cpf; A = Af; Y = Yf; }
    else          { X = Xb; Dl = Db; Bp = Bpb; Cp = Cpb; A = Ab; Y = Yb; }
    bool rev = (dir == 1);

    int b_  = blockIdx.y;
    int tid = threadIdx.x;
    int e   = blockIdx.x * 256 + tid;
    size_t baseRow = (size_t)b_ * Mm;

    float a[Nn];
    #pragma unroll
    for (int q = 0; q < 4; q++) {
        float4 av = *(const float4*)(A + (size_t)e*Nn + q*4);
        a[q*4+0] = av.x; a[q*4+1] = av.y; a[q*4+2] = av.z; a[q*4+3] = av.w;
    }
    float h[Nn];
    #pragma unroll
    for (int n = 0; n < Nn; n++) h[n] = 0.f;

    __shared__ float sBC[2][8][32];
    int ls = tid >> 5;
    int ln = tid & 31;

    float xb[8], db[8];
    #pragma unroll
    for (int s = 0; s < 8; s++) {
        int m = rev ? (Mm - 1 - s) : s;
        size_t idx = (baseRow + m) * Ee + e;
        xb[s] = X[idx]; db[s] = Dl[idx];
    }
    {
        int m = rev ? (Mm - 1 - ls) : ls;
        sBC[0][ls][ln] = (ln < Nn) ? Bp[(baseRow + m)*Nn + ln]
                                   : Cp[(baseRow + m)*Nn + (ln - Nn)];
    }
    __syncthreads();

    const int NCH = Mm / 8;
    for (int c = 0; c < NCH; ++c) {
        int buf = c & 1;
        float nx[8], nd[8], nbc = 0.f;
        bool more = (c + 1 < NCH);
        if (more) {
            #pragma unroll
            for (int s = 0; s < 8; s++) {
                int t = (c + 1) * 8 + s;
                int m = rev ? (Mm - 1 - t) : t;
                size_t idx = (baseRow + m) * Ee + e;
                nx[s] = X[idx]; nd[s] = Dl[idx];
            }
            int t = (c + 1) * 8 + ls;
            int m = rev ? (Mm - 1 - t) : t;
            nbc = (ln < Nn) ? Bp[(baseRow + m)*Nn + ln]
                            : Cp[(baseRow + m)*Nn + (ln - Nn)];
        }
        #pragma unroll
        for (int s = 0; s < 8; s++) {
            float dv = db[s], xv = xb[s];
            float dx = dv * xv;
            float yv0 = 0.f, yv1 = 0.f;
            #pragma unroll
            for (int n = 0; n < Nn; n += 2) {
                float Bn0 = sBC[buf][s][n];
                float Cn0 = sBC[buf][s][Nn + n];
                float Bn1 = sBC[buf][s][n + 1];
                float Cn1 = sBC[buf][s][Nn + n + 1];
                h[n]     = fmaf(dv * a[n],     h[n],     dx * Bn0);
                h[n + 1] = fmaf(dv * a[n + 1], h[n + 1], dx * Bn1);
                yv0 = fmaf(h[n],     Cn0, yv0);
                yv1 = fmaf(h[n + 1], Cn1, yv1);
            }
            int t = c * 8 + s;
            int m = rev ? (Mm - 1 - t) : t;
            Y[(baseRow + m) * Ee + e] = yv0 + yv1;
        }
        if (more) {
            #pragma unroll
            for (int s = 0; s < 8; s++) { xb[s] = nx[s]; db[s] = nd[s]; }
            sBC[buf ^ 1][ls][ln] = nbc;
        }
        __syncthreads();
    }
}

// ---------------- gate multiply: writes bf16 (final GEMM A operand) --------------
__global__ void mul_kernel(const float4* __restrict__ a, const float4* __restrict__ b,
                           const float4* __restrict__ z, uint2* __restrict__ o, int n4)
{
    for (int i = blockIdx.x * blockDim.x + threadIdx.x; i < n4; i += gridDim.x * blockDim.x) {
        float4 A = a[i], Bv = b[i], Z = z[i];
        o[i] = make_uint2(packbf((A.x + Bv.x) * Z.x, (A.y + Bv.y) * Z.y),
                          packbf((A.z + Bv.z) * Z.z, (A.w + Bv.w) * Z.w));
    }
}

// ---------------- launch ----------------
// Launch order arranged so the 6th launch (ncu -s 5 -c 1) is the forward conv —
// the largest GEMM — instead of a trivial cvt kernel.
extern "C" void kernel_launch(void* const* d_in, const int* in_sizes, int n_in,
                              void* d_out, int out_size)
{
    const float* t    = (const float*)d_in[0];
    const float* ln_g = (const float*)d_in[1];
    const float* ln_b = (const float*)d_in[2];
    const float* Wx   = (const float*)d_in[3];
    const float* bx   = (const float*)d_in[4];
    const float* Wz   = (const float*)d_in[5];
    const float* bz   = (const float*)d_in[6];
    const float* Wcf  = (const float*)d_in[7];
    const float* bcf  = (const float*)d_in[8];
    const float* Wcb  = (const float*)d_in[9];
    const float* bcb  = (const float*)d_in[10];
    const float* WBf  = (const float*)d_in[11];
    const float* bBf  = (const float*)d_in[12];
    const float* WCf  = (const float*)d_in[13];
    const float* bCf  = (const float*)d_in[14];
    const float* WDf  = (const float*)d_in[15];
    const float* bDf  = (const float*)d_in[16];
    const float* WBb  = (const float*)d_in[17];
    const float* bBb  = (const float*)d_in[18];
    const float* WCb  = (const float*)d_in[19];
    const float* bCb  = (const float*)d_in[20];
    const float* WDb  = (const float*)d_in[21];
    const float* bDb  = (const float*)d_in[22];
    const float* Abf  = (const float*)d_in[23];
    const float* Abb  = (const float*)d_in[24];
    const float* dbf  = (const float*)d_in[25];
    const float* dbb  = (const float*)d_in[26];
    const float* WT   = (const float*)d_in[27];
    const float* bT   = (const float*)d_in[28];
    float* out = (float*)d_out;

    void *p;
    cudaGetSymbolAddress(&p, g_xn_h);   __nv_bfloat16* xn_h  = (__nv_bfloat16*)p;
    cudaGetSymbolAddress(&p, g_xpj_h);  __nv_bfloat16* xpj_h = (__nv_bfloat16*)p;
    cudaGetSymbolAddress(&p, g_zs);     float* zs    = (float*)p;
    cudaGetSymbolAddress(&p, g_xpf);    float* xpf   = (float*)p;
    cudaGetSymbolAddress(&p, g_xpb);    float* xpb   = (float*)p;
    cudaGetSymbolAddress(&p, g_xpf_h);  __nv_bfloat16* xpf_h = (__nv_bfloat16*)p;
    cudaGetSymbolAddress(&p, g_xpb_h);  __nv_bfloat16* xpb_h = (__nv_bfloat16*)p;
    cudaGetSymbolAddress(&p, g_df);     float* df    = (float*)p;
    cudaGetSymbolAddress(&p, g_dbk);    float* dbk   = (float*)p;
    cudaGetSymbolAddress(&p, g_yf);     float* yf    = (float*)p;
    cudaGetSymbolAddress(&p, g_yb);     float* yb    = (float*)p;
    cudaGetSymbolAddress(&p, g_gate_h); __nv_bfloat16* gate_h = (__nv_bfloat16*)p;
    cudaGetSymbolAddress(&p, g_Bpf);    float* Bpf = (float*)p;
    cudaGetSymbolAddress(&p, g_Cpf);    float* Cpf = (float*)p;
    cudaGetSymbolAddress(&p, g_Bpb);    float* Bpb = (float*)p;
    cudaGetSymbolAddress(&p, g_Cpb);    float* Cpb = (float*)p;
    cudaGetSymbolAddress(&p, g_wcf_h);  __nv_bfloat16* wcf_h = (__nv_bfloat16*)p;
    cudaGetSymbolAddress(&p, g_wcb_h);  __nv_bfloat16* wcb_h = (__nv_bfloat16*)p;
    cudaGetSymbolAddress(&p, g_wx_h);   __nv_bfloat16* wx_h  = (__nv_bfloat16*)p;
    cudaGetSymbolAddress(&p, g_wz_h);   __nv_bfloat16* wz_h  = (__nv_bfloat16*)p;
    cudaGetSymbolAddress(&p, g_wdf_h);  __nv_bfloat16* wdf_h = (__nv_bfloat16*)p;
    cudaGetSymbolAddress(&p, g_wdb_h);  __nv_bfloat16* wdb_h = (__nv_bfloat16*)p;
    cudaGetSymbolAddress(&p, g_wt_h);   __nv_bfloat16* wt_h  = (__nv_bfloat16*)p;

    dim3 gEB(Ee/128, BMr/128);

    // launches 1-5: ln, cvt Wx, cvt Wz, gemm Wx, repack Wcf
    ln_kernel<<<BMr, 256>>>(t, ln_g, ln_b, xn_h);                                   // 1
    cvt_kernel<<<(Ee*Dd/4 + 255)/256, 256>>>((const float4*)Wx, (uint2*)wx_h, Ee*Dd/4);  // 2
    cvt_kernel<<<(Ee*Dd/4 + 255)/256, 256>>>((const float4*)Wz, (uint2*)wz_h, Ee*Dd/4);  // 3
    gemm_bf<0,1><<<gEB, 256>>>(xn_h, wx_h, bx, nullptr, nullptr, nullptr, xpj_h, Ee, Dd); // 4
    repack_conv<<<(Ee*Ee + 255)/256, 256>>>(Wcf, wcf_h);                             // 5

    // launch 6: forward conv — PROFILED by ncu (-s 5 -c 1)
    conv_bf<<<gEB, 256>>>(xpj_h, wcf_h, bcf, xpf, xpf_h);                            // 6

    // remaining producers + consumers
    gemm_bf<1,0><<<gEB, 256>>>(xn_h, wz_h, bz, nullptr, nullptr, zs, nullptr, Ee, Dd); // 7
    repack_conv<<<(Ee*Ee + 255)/256, 256>>>(Wcb, wcb_h);                             // 8
    conv_bf<<<gEB, 256>>>(xpj_h, wcb_h, bcb, xpb, xpb_h);                            // 9

    cvt_kernel<<<(Ee*Ee/4 + 255)/256, 256>>>((const float4*)WDf, (uint2*)wdf_h, Ee*Ee/4);
    cvt_kernel<<<(Ee*Ee/4 + 255)/256, 256>>>((const float4*)WDb, (uint2*)wdb_h, Ee*Ee/4);
    cvt_kernel<<<(Dd*Ee/4 + 255)/256, 256>>>((const float4*)WT,  (uint2*)wt_h,  Dd*Ee/4);

    bc_kernel<<<BMr/256, 256>>>(xpf, WBf, bBf, WCf, bCf, Bpf, Cpf);
    bc_kernel<<<BMr/256, 256>>>(xpb, WBb, bBb, WCb, bCb, Bpb, Cpb);

    gemm_bf<2,0><<<gEB, 256>>>(xpf_h, wdf_h, bDf, dbf, nullptr, df,  nullptr, Ee, Ee);
    gemm_bf<2,0><<<gEB, 256>>>(xpb_h, wdb_h, bDb, dbb, nullptr, dbk, nullptr, Ee, Ee);

    scan_kernel<<<dim3(Ee/256, Bb, 2), 256>>>(xpf, df, Bpf, Cpf, Abf, yf,
                                              xpb, dbk, Bpb, Cpb, Abb, yb);

    mul_kernel<<<2048, 256>>>((const float4*)yf, (const float4*)yb,
                              (const float4*)zs, (uint2*)gate_h,
                              (BMr * Ee) / 4);

    gemm_bf<0,0><<<dim3(Dd/128, BMr/128), 256>>>(gate_h, wt_h, bT, nullptr, t, out, nullptr, Dd, Ee);
}